// round 13
// baseline (speedup 1.0000x reference)
#include <cuda_runtime.h>
#include <cuda_bf16.h>
#include <math.h>

// Problem constants (fixed shapes)
#define BB 4
#define SS 2048
#define DD 1024
#define HH 16
#define DH 64
#define LL 1536

// ---------------- scratch (device globals; no allocations allowed) ----------
__device__ int   g_idx[BB * LL];           // kept indices per batch
__device__ int   g_len[BB];                // kept lengths
__device__ int   g_masksel;                // which candidate is the mask (0/1)
__device__ int   g_maskdt;                 // 0=u8, 1=i32, 2=f32

// bf16 split copies (hi + lo, x = hi + lo to ~2^-17)
__device__ __nv_bfloat16 g_qh[BB * SS * DD], g_ql[BB * SS * DD];
__device__ __nv_bfloat16 g_kh[BB * SS * DD], g_kl[BB * SS * DD];
__device__ __nv_bfloat16 g_vh[BB * SS * DD], g_vl[BB * SS * DD];
__device__ __nv_bfloat16 g_wqh[DD * DD], g_wql[DD * DD];
__device__ __nv_bfloat16 g_wkh[DD * DD], g_wkl[DD * DD];
__device__ __nv_bfloat16 g_wvh[DD * DD], g_wvl[DD * DD];
__device__ __nv_bfloat16 g_woh[DD * DD], g_wol[DD * DD];
__device__ __nv_bfloat16 g_Ohi[BB * LL * DD], g_Olo[BB * LL * DD];  // flash out
// RoPE'd attention operands + projected V, split bf16
__device__ __nv_bfloat16 g_Qrh[BB * HH * LL * DH], g_Qrl[BB * HH * LL * DH];
__device__ __nv_bfloat16 g_Krh[BB * HH * SS * DH], g_Krl[BB * HH * SS * DH];
__device__ __nv_bfloat16 g_Vph[BB * HH * SS * DH], g_Vpl[BB * HH * SS * DH];

// ---------------- helpers -----------------------------------------------------
__device__ __forceinline__ unsigned s2u(const void* p) {
    return (unsigned)__cvta_generic_to_shared(p);
}
__device__ __forceinline__ void cpa16(unsigned dst, const void* src) {
    asm volatile("cp.async.cg.shared.global [%0], [%1], 16;\n" :: "r"(dst), "l"(src));
}
__device__ __forceinline__ void cpa_commit() {
    asm volatile("cp.async.commit_group;\n");
}
__device__ __forceinline__ void cpa_wait0() {
    asm volatile("cp.async.wait_group 0;\n");
}
__device__ __forceinline__ float ex2f(float x) {
    float y;
    asm("ex2.approx.f32 %0, %1;" : "=f"(y) : "f"(x));
    return y;
}
__device__ __forceinline__ void packsplit(float x, float y, unsigned& hi, unsigned& lo) {
    union { __nv_bfloat16 h[2]; unsigned u; } H, L;
    __nv_bfloat16 hx = __float2bfloat16(x), hy = __float2bfloat16(y);
    H.h[0] = hx;
    H.h[1] = hy;
    L.h[0] = __float2bfloat16(x - __bfloat162float(hx));
    L.h[1] = __float2bfloat16(y - __bfloat162float(hy));
    hi = H.u;
    lo = L.u;
}
__device__ __forceinline__ void mma_bf16(float* d, const unsigned* a,
                                         unsigned b0, unsigned b1) {
    asm volatile(
        "mma.sync.aligned.m16n8k16.row.col.f32.bf16.bf16.f32 "
        "{%0,%1,%2,%3}, {%4,%5,%6,%7}, {%8,%9}, {%0,%1,%2,%3};\n"
        : "+f"(d[0]), "+f"(d[1]), "+f"(d[2]), "+f"(d[3])
        : "r"(a[0]), "r"(a[1]), "r"(a[2]), "r"(a[3]), "r"(b0), "r"(b1));
}
__device__ __forceinline__ void ldm4(unsigned* r, unsigned a) {
    asm volatile("ldmatrix.sync.aligned.m8n8.x4.shared.b16 {%0,%1,%2,%3}, [%4];\n"
                 : "=r"(r[0]), "=r"(r[1]), "=r"(r[2]), "=r"(r[3]) : "r"(a));
}
__device__ __forceinline__ void ldm4t(unsigned* r, unsigned a) {
    asm volatile("ldmatrix.sync.aligned.m8n8.x4.trans.shared.b16 {%0,%1,%2,%3}, [%4];\n"
                 : "=r"(r[0]), "=r"(r[1]), "=r"(r[2]), "=r"(r[3]) : "r"(a));
}

// ---------------- 0) mask dtype/slot detection ------------------------------
__global__ void detect_mask_kernel(const void* a, const void* b,
                                   int* sel, int* dt) {
    __shared__ int bad[2][3];
    if (threadIdx.x < 6) (&bad[0][0])[threadIdx.x] = 0;
    __syncthreads();
    for (int c = 0; c < 2; c++) {
        const unsigned* p = (const unsigned*)(c ? b : a);
        for (int i = threadIdx.x; i < 2048; i += blockDim.x) {
            unsigned v = p[i];
            if (v > 1u) bad[c][1] = 1;
            if (v != 0u && v != 0x3F800000u) bad[c][2] = 1;
            if ((v | (v >> 8) | (v >> 16) | (v >> 24)) & 0xFEu) bad[c][0] = 1;
        }
    }
    __syncthreads();
    if (threadIdx.x == 0) {
        int s = -1, d = 0;
        for (int c = 0; c < 2 && s < 0; c++) {
            if (!bad[c][1]) { s = c; d = 1; }
            else if (!bad[c][2]) { s = c; d = 2; }
            else if (!bad[c][0]) { s = c; d = 0; }
        }
        if (s < 0) { s = 1; d = 0; }
        *sel = s;
        *dt = d;
    }
}

// ---------------- 1) ragged compaction (stable) -----------------------------
__global__ void compact_kernel(const void* candA, const void* candB,
                               const int* __restrict__ sel,
                               const int* __restrict__ dt,
                               int* __restrict__ idxb, int* __restrict__ lenb) {
    int b = blockIdx.x;
    int lane = threadIdx.x;  // 32 threads
    const void* mp = (*sel) ? candB : candA;
    int wide = (*dt != 0);
    int base = lane * 64;

    int kept[64];
    int cnt = 0;
    if (wide) {
        const unsigned* sp = (const unsigned*)mp + b * SS;
        for (int t = 0; t < 64; t++) { kept[t] = (sp[base + t] != 0u); cnt += kept[t]; }
    } else {
        const unsigned char* sp = (const unsigned char*)mp + b * SS;
        for (int t = 0; t < 64; t++) { kept[t] = (sp[base + t] != 0); cnt += kept[t]; }
    }

    int inc = cnt;
    for (int o = 1; o < 32; o <<= 1) {
        int v = __shfl_up_sync(0xffffffffu, inc, o);
        if (lane >= o) inc += v;
    }
    int off = inc - cnt;
    int total = __shfl_sync(0xffffffffu, inc, 31);
    for (int t = 0; t < 64; t++) {
        if (kept[t]) {
            if (off < LL) idxb[b * LL + off] = base + t;
            off++;
        }
    }
    int tot = min(total, LL);
    if (lane == 0) lenb[b] = tot;
    for (int i = tot + lane; i < LL; i += 32) idxb[b * LL + i] = 0;
}

// ---------------- 1b) fp32 -> bf16 hi/lo split --------------------------------
__global__ void split_kernel(const float4* __restrict__ in, uint2* __restrict__ hi,
                             uint2* __restrict__ lo, int n4) {
    int i = blockIdx.x * 256 + threadIdx.x;
    if (i >= n4) return;
    float4 v = in[i];
    union { __nv_bfloat16 b4[4]; uint2 u; } H, L;
    float vv[4] = {v.x, v.y, v.z, v.w};
#pragma unroll
    for (int k = 0; k < 4; k++) {
        __nv_bfloat16 h = __float2bfloat16(vv[k]);
        H.b4[k] = h;
        L.b4[k] = __float2bfloat16(vv[k] - __bfloat162float(h));
    }
    hi[i] = H.u;
    lo[i] = L.u;
}

// ---------------- 2) split-bf16 tensor-core GEMM ------------------------------
// C = A * W^T. Tile 128x128, BK=32, 256 threads (8 warps), warp tile 32x64.
// MODE 0: Q proj + fused RoPE -> split bf16 [b,h,i,dh]; skip invalid tiles
// MODE 1: K proj + fused RoPE -> split bf16 [b,h,s,dh]
// MODE 2: O proj (direct; store fp32 to out, zero invalid rows; skip->zeros)
//         mhalf>=0 selects i-range half: m0 = b*LL + mhalf*768 + t*128, grid.x=24
// MODE 3: V proj (direct rows; scatter split bf16 [b,h,s,dh])
#define GBM 128
#define GBN 128
#define GBK 32
#define SAW 40  // smem row stride in bf16 elems (80B: 16B-aligned, conflict-free)
#define MAT_ELEMS (128 * SAW)
#define MAT_BYTES (MAT_ELEMS * 2)
#define GSMEM_BYTES (2 * 4 * MAT_BYTES + 768)
#define QSCALE 0.18033688011112042f

template <int MODE>
__global__ void __launch_bounds__(256, 2) bgemm_kernel(
    const __nv_bfloat16* __restrict__ Ahi, const __nv_bfloat16* __restrict__ Alo,
    const __nv_bfloat16* __restrict__ Bhi, const __nv_bfloat16* __restrict__ Blo,
    float* __restrict__ C,
    __nv_bfloat16* __restrict__ Chi, __nv_bfloat16* __restrict__ Clo,
    const int* __restrict__ idxb, const int* __restrict__ lenb,
    const float* __restrict__ invf, int mhalf) {
    extern __shared__ char sm[];
    // layout per buf: AH, AL, BH, BL each MAT_BYTES
    __nv_bfloat16* base0 = (__nv_bfloat16*)sm;
    int* rowSrc = (int*)(sm + 2 * 4 * MAT_BYTES);

    int tid = threadIdx.x;
    int m0;
    if (MODE == 2 && mhalf >= 0) {
        int bx = blockIdx.x;
        m0 = (bx / 6) * LL + mhalf * 768 + (bx % 6) * GBM;
    } else {
        m0 = blockIdx.x * GBM;
    }
    int n0 = blockIdx.y * GBN;

    // Tile skip: tiles never span batches for MODE 0/2.
    if (MODE == 0 || MODE == 2) {
        int b = m0 / LL;
        if ((m0 - b * LL) >= lenb[b]) {
            if (MODE == 2) {
                for (int t = tid; t < GBM * GBN / 4; t += 256) {
                    int r = t >> 5, c4 = t & 31;
                    *(float4*)&C[(size_t)(m0 + r) * DD + n0 + c4 * 4] =
                        make_float4(0.f, 0.f, 0.f, 0.f);
                }
            }
            return;
        }
    }

    for (int r = tid; r < GBM; r += 256) {
        int m = m0 + r;
        int src;
        if (MODE == 0) {
            int b = m / LL, i = m - b * LL;
            int len = lenb[b];
            int iv = (i < len) ? idxb[b * LL + i] : 0;
            src = b * SS + iv;
        } else {
            src = m;
        }
        rowSrc[r] = src;
    }
    __syncthreads();

    auto issue = [&](int buf, int kt) {
        __nv_bfloat16* aH = base0 + buf * 4 * MAT_ELEMS;
        __nv_bfloat16* aL = aH + MAT_ELEMS;
        __nv_bfloat16* bH = aL + MAT_ELEMS;
        __nv_bfloat16* bL = bH + MAT_ELEMS;
#pragma unroll
        for (int it = 0; it < 2; it++) {
            int ca = tid + it * 256;          // 0..511: row=ca>>2, 16B chunk=ca&3
            int row = ca >> 2, ch = ca & 3;
            size_t soA = (size_t)rowSrc[row] * DD + kt + ch * 8;
            cpa16(s2u(&aH[row * SAW + ch * 8]), Ahi + soA);
            cpa16(s2u(&aL[row * SAW + ch * 8]), Alo + soA);
            size_t soB = (size_t)(n0 + row) * DD + kt + ch * 8;
            cpa16(s2u(&bH[row * SAW + ch * 8]), Bhi + soB);
            cpa16(s2u(&bL[row * SAW + ch * 8]), Blo + soB);
        }
        cpa_commit();
    };

    float acc[2][8][4];
#pragma unroll
    for (int mt = 0; mt < 2; mt++)
#pragma unroll
        for (int nt = 0; nt < 8; nt++)
#pragma unroll
            for (int k = 0; k < 4; k++) acc[mt][nt][k] = 0.f;

    int lane = tid & 31, warp = tid >> 5;
    int wm = (warp & 3) * 32, wn = (warp >> 2) * 64;
    int grp = lane >> 3, gr = lane & 7;

    issue(0, 0);

    const int NK = DD / GBK;  // 32
    for (int s = 0; s < NK; s++) {
        cpa_wait0();
        __syncthreads();
        if (s + 1 < NK) issue((s + 1) & 1, (s + 1) * GBK);

        int buf = s & 1;
        unsigned aHb = s2u(base0 + buf * 4 * MAT_ELEMS);
        unsigned aLb = aHb + MAT_BYTES;
        unsigned bHb = aLb + MAT_BYTES;
        unsigned bLb = bHb + MAT_BYTES;

#pragma unroll
        for (int ks = 0; ks < 2; ks++) {
            int k = ks * 16;
            unsigned AH[2][4], AL[2][4];
#pragma unroll
            for (int mt = 0; mt < 2; mt++) {
                unsigned off = ((wm + mt * 16 + (lane & 15)) * SAW + k +
                                (lane >> 4) * 8) * 2;
                ldm4(AH[mt], aHb + off);
                ldm4(AL[mt], aLb + off);
            }
#pragma unroll
            for (int half = 0; half < 4; half++) {
                unsigned ad = ((wn + half * 16 + ((grp & 2) << 2) + gr) * SAW + k +
                               (grp & 1) * 8) * 2;
                unsigned tH[4], tL[4];
                ldm4(tH, bHb + ad);
                ldm4(tL, bLb + ad);
#pragma unroll
                for (int mt = 0; mt < 2; mt++) {
                    mma_bf16(acc[mt][2 * half], AH[mt], tH[0], tH[1]);
                    mma_bf16(acc[mt][2 * half], AH[mt], tL[0], tL[1]);
                    mma_bf16(acc[mt][2 * half], AL[mt], tH[0], tH[1]);
                    mma_bf16(acc[mt][2 * half + 1], AH[mt], tH[2], tH[3]);
                    mma_bf16(acc[mt][2 * half + 1], AH[mt], tL[2], tL[3]);
                    mma_bf16(acc[mt][2 * half + 1], AL[mt], tH[2], tH[3]);
                }
            }
        }
    }

    int r = lane >> 2, c2 = (lane & 3) * 2;

    if (MODE == 0 || MODE == 1) {
        // Fused RoPE epilogue. Warp tile = 64 cols = one head; column dh pairs
        // with dh+32 held by the SAME thread (nt and nt+4).
        int h = (n0 + wn) >> 6;
#pragma unroll
        for (int mt = 0; mt < 2; mt++)
#pragma unroll
            for (int half = 0; half < 2; half++) {
                int m = m0 + wm + mt * 16 + r + half * 8;
                int pos;
                size_t obase;
                if (MODE == 0) {
                    int b = m / LL, i = m - b * LL;
                    pos = rowSrc[m - m0] - b * SS;
                    obase = ((size_t)(b * HH + h) * LL + i) * DH;
                } else {
                    int b = m >> 11, ss = m & (SS - 1);
                    pos = ss;
                    obase = ((size_t)(b * HH + h) * SS + ss) * DH;
                }
                float fp = (float)pos;
#pragma unroll
                for (int nt = 0; nt < 4; nt++) {
                    int dh = nt * 8 + c2;
                    float s0, c0, s1, c1;
                    sincosf(fp * invf[dh], &s0, &c0);
                    sincosf(fp * invf[dh + 1], &s1, &c1);
                    float x1a = acc[mt][nt][half * 2 + 0];
                    float x1b = acc[mt][nt][half * 2 + 1];
                    float x2a = acc[mt][nt + 4][half * 2 + 0];
                    float x2b = acc[mt][nt + 4][half * 2 + 1];
                    float o1a = x1a * c0 - x2a * s0;
                    float o2a = x2a * c0 + x1a * s0;
                    float o1b = x1b * c1 - x2b * s1;
                    float o2b = x2b * c1 + x1b * s1;
                    if (MODE == 0) {
                        o1a *= QSCALE; o1b *= QSCALE;
                        o2a *= QSCALE; o2b *= QSCALE;
                    }
                    unsigned hi, lo;
                    packsplit(o1a, o1b, hi, lo);
                    *(unsigned*)&Chi[obase + dh] = hi;
                    *(unsigned*)&Clo[obase + dh] = lo;
                    packsplit(o2a, o2b, hi, lo);
                    *(unsigned*)&Chi[obase + dh + 32] = hi;
                    *(unsigned*)&Clo[obase + dh + 32] = lo;
                }
            }
        return;
    }

#pragma unroll
    for (int mt = 0; mt < 2; mt++)
#pragma unroll
        for (int nt = 0; nt < 8; nt++) {
            int n = n0 + wn + nt * 8 + c2;
#pragma unroll
            for (int half = 0; half < 2; half++) {
                int m = m0 + wm + mt * 16 + r + half * 8;
                float v0 = acc[mt][nt][half * 2 + 0];
                float v1 = acc[mt][nt][half * 2 + 1];
                if (MODE == 3) {
                    int b = m >> 11, ss = m & (SS - 1);
                    int h = n >> 6, dh = n & 63;
                    unsigned hi, lo;
                    packsplit(v0, v1, hi, lo);
                    size_t o = (((size_t)(b * HH + h) * SS) + ss) * DH + dh;
                    *(unsigned*)&Chi[o] = hi;
                    *(unsigned*)&Clo[o] = lo;
                } else {
                    int b = m / LL, i = m - b * LL;
                    bool valid = (i < lenb[b]);
                    float2 o = valid ? make_float2(v0, v1) : make_float2(0.f, 0.f);
                    *(float2*)&C[(size_t)m * DD + n] = o;
                }
            }
        }
}

// ---------------- 4) flash attention on tensor cores --------------------------
// K/V tiles double-buffered via cp.async. qtbase splits the q-tile range so
// the light (low-q0, causal-short) half can run first and overlap O-proj.
#define FT_PITCH 72
#define FT_TILE (64 * FT_PITCH)
#define FT_SMEM (10 * FT_TILE * 2 + 256)

__global__ void __launch_bounds__(128, 2) flashmma_kernel(
    const __nv_bfloat16* __restrict__ Qh, const __nv_bfloat16* __restrict__ Ql,
    const __nv_bfloat16* __restrict__ Kh, const __nv_bfloat16* __restrict__ Kl,
    const __nv_bfloat16* __restrict__ Vh, const __nv_bfloat16* __restrict__ Vl,
    __nv_bfloat16* __restrict__ Ohi, __nv_bfloat16* __restrict__ Olo,
    const int* __restrict__ idxb, const int* __restrict__ lenb, int qtbase) {
    int bhid = blockIdx.x;
    int b = bhid >> 4, h = bhid & 15;
    int q0 = (blockIdx.y + qtbase) << 6;
    int len = lenb[b];
    if (q0 >= len) return;

    extern __shared__ __nv_bfloat16 sb[];
    __nv_bfloat16* Qsh = sb;
    __nv_bfloat16* Qsl = Qsh + FT_TILE;
    __nv_bfloat16* KV0 = Qsl + FT_TILE;  // per buf: Ksh,Ksl,Vsh,Vsl
    int* qcap = (int*)(sb + 10 * FT_TILE);

    int tid = threadIdx.x, lane = tid & 31, warp = tid >> 5;
    int grp = lane >> 3, gr = lane & 7;
    const size_t hb = (size_t)(b * HH + h);

    const __nv_bfloat16* Kgh = Kh + hb * SS * DH;
    const __nv_bfloat16* Kgl = Kl + hb * SS * DH;
    const __nv_bfloat16* Vgh = Vh + hb * SS * DH;
    const __nv_bfloat16* Vgl = Vl + hb * SS * DH;

    auto issueKV = [&](int buf, int t) {
        __nv_bfloat16* kH = KV0 + buf * 4 * FT_TILE;
#pragma unroll
        for (int it = 0; it < 4; it++) {
            int ca = tid + it * 128;
            int row = ca >> 3, col = (ca & 7) * 8;
            size_t go = (size_t)(t * 64 + row) * DH + col;
            unsigned so = s2u(kH + row * FT_PITCH + col);
            cpa16(so, Kgh + go);
            cpa16(so + FT_TILE * 2, Kgl + go);
            cpa16(so + FT_TILE * 4, Vgh + go);
            cpa16(so + FT_TILE * 6, Vgl + go);
        }
        cpa_commit();
    };

    const __nv_bfloat16* Qgh = Qh + (hb * LL + q0) * DH;
    const __nv_bfloat16* Qgl = Ql + (hb * LL + q0) * DH;
#pragma unroll
    for (int it = 0; it < 4; it++) {
        int c = tid + it * 128;
        int r = c >> 3, col = (c & 7) * 8;
        *(uint4*)&Qsh[r * FT_PITCH + col] = *(const uint4*)&Qgh[r * DH + col];
        *(uint4*)&Qsl[r * FT_PITCH + col] = *(const uint4*)&Qgl[r * DH + col];
    }
    if (tid < 64) {
        int i = q0 + tid;
        qcap[tid] = (i < len) ? idxb[b * LL + i] : 0;
    }
    issueKV(0, 0);
    __syncthreads();

    int nv = min(64, len - q0);
    int ntiles = (qcap[nv - 1] >> 6) + 1;
    int r1 = lane >> 2, cq = lane & 3;
    int cap1 = qcap[warp * 16 + r1];
    int cap2 = qcap[warp * 16 + r1 + 8];

    // hoist Q fragments
    unsigned qshb = s2u(Qsh), qslb = s2u(Qsl);
    unsigned QH[4][4], QL[4][4];
#pragma unroll
    for (int ks = 0; ks < 4; ks++) {
        unsigned off = ((warp * 16 + (lane & 15)) * FT_PITCH + ks * 16 +
                        (lane >> 4) * 8) * 2;
        ldm4(QH[ks], qshb + off);
        ldm4(QL[ks], qslb + off);
    }

    float mi1 = -1e30f, mi2 = -1e30f, li1 = 0.f, li2 = 0.f;
    float oacc[8][4];
#pragma unroll
    for (int dt = 0; dt < 8; dt++)
#pragma unroll
        for (int k = 0; k < 4; k++) oacc[dt][k] = 0.f;

    for (int t = 0; t < ntiles; t++) {
        cpa_wait0();
        __syncthreads();
        if (t + 1 < ntiles) issueKV((t + 1) & 1, t + 1);

        int buf = t & 1;
        unsigned kshb = s2u(KV0 + buf * 4 * FT_TILE);
        unsigned kslb = kshb + FT_TILE * 2;
        unsigned vshb = kslb + FT_TILE * 2;
        unsigned vslb = vshb + FT_TILE * 2;

        float sacc[8][4];
#pragma unroll
        for (int nt = 0; nt < 8; nt++)
#pragma unroll
            for (int k = 0; k < 4; k++) sacc[nt][k] = 0.f;

#pragma unroll
        for (int ks = 0; ks < 4; ks++) {
            int k = ks * 16;
#pragma unroll
            for (int half = 0; half < 4; half++) {
                unsigned ad = ((half * 16 + ((grp & 2) << 2) + gr) * FT_PITCH + k +
                               (grp & 1) * 8) * 2;
                unsigned tH[4], tL[4];
                ldm4(tH, kshb + ad);
                ldm4(tL, kslb + ad);
                mma_bf16(sacc[2 * half], QH[ks], tH[0], tH[1]);
                mma_bf16(sacc[2 * half], QH[ks], tL[0], tL[1]);
                mma_bf16(sacc[2 * half], QL[ks], tH[0], tH[1]);
                mma_bf16(sacc[2 * half + 1], QH[ks], tH[2], tH[3]);
                mma_bf16(sacc[2 * half + 1], QH[ks], tL[2], tL[3]);
                mma_bf16(sacc[2 * half + 1], QL[ks], tH[2], tH[3]);
            }
        }

        float mn1 = mi1, mn2 = mi2;
#pragma unroll
        for (int nt = 0; nt < 8; nt++) {
            int jg = (t << 6) + nt * 8 + cq * 2;
            sacc[nt][0] = (jg <= cap1) ? sacc[nt][0] : -1e30f;
            sacc[nt][1] = (jg + 1 <= cap1) ? sacc[nt][1] : -1e30f;
            sacc[nt][2] = (jg <= cap2) ? sacc[nt][2] : -1e30f;
            sacc[nt][3] = (jg + 1 <= cap2) ? sacc[nt][3] : -1e30f;
            mn1 = fmaxf(mn1, fmaxf(sacc[nt][0], sacc[nt][1]));
            mn2 = fmaxf(mn2, fmaxf(sacc[nt][2], sacc[nt][3]));
        }
        mn1 = fmaxf(mn1, __shfl_xor_sync(0xffffffffu, mn1, 1));
        mn1 = fmaxf(mn1, __shfl_xor_sync(0xffffffffu, mn1, 2));
        mn2 = fmaxf(mn2, __shfl_xor_sync(0xffffffffu, mn2, 1));
        mn2 = fmaxf(mn2, __shfl_xor_sync(0xffffffffu, mn2, 2));
        float corr1 = ex2f(mi1 - mn1), corr2 = ex2f(mi2 - mn2);
        mi1 = mn1;
        mi2 = mn2;
        float rs1 = 0.f, rs2 = 0.f;
#pragma unroll
        for (int nt = 0; nt < 8; nt++) {
            sacc[nt][0] = ex2f(sacc[nt][0] - mn1);
            sacc[nt][1] = ex2f(sacc[nt][1] - mn1);
            sacc[nt][2] = ex2f(sacc[nt][2] - mn2);
            sacc[nt][3] = ex2f(sacc[nt][3] - mn2);
            rs1 += sacc[nt][0] + sacc[nt][1];
            rs2 += sacc[nt][2] + sacc[nt][3];
        }
        rs1 += __shfl_xor_sync(0xffffffffu, rs1, 1);
        rs1 += __shfl_xor_sync(0xffffffffu, rs1, 2);
        rs2 += __shfl_xor_sync(0xffffffffu, rs2, 1);
        rs2 += __shfl_xor_sync(0xffffffffu, rs2, 2);
        li1 = li1 * corr1 + rs1;
        li2 = li2 * corr2 + rs2;
#pragma unroll
        for (int dt = 0; dt < 8; dt++) {
            oacc[dt][0] *= corr1;
            oacc[dt][1] *= corr1;
            oacc[dt][2] *= corr2;
            oacc[dt][3] *= corr2;
        }

#pragma unroll
        for (int ks = 0; ks < 4; ks++) {
            unsigned ah[4], al[4];
            packsplit(sacc[2 * ks][0], sacc[2 * ks][1], ah[0], al[0]);
            packsplit(sacc[2 * ks][2], sacc[2 * ks][3], ah[1], al[1]);
            packsplit(sacc[2 * ks + 1][0], sacc[2 * ks + 1][1], ah[2], al[2]);
            packsplit(sacc[2 * ks + 1][2], sacc[2 * ks + 1][3], ah[3], al[3]);
#pragma unroll
            for (int dtp = 0; dtp < 4; dtp++) {
                unsigned off = ((ks * 16 + (lane & 15)) * FT_PITCH + dtp * 16 +
                                (lane >> 4) * 8) * 2;
                unsigned BH[4], BL[4];
                ldm4t(BH, vshb + off);
                ldm4t(BL, vslb + off);
                mma_bf16(oacc[2 * dtp], ah, BH[0], BH[1]);
                mma_bf16(oacc[2 * dtp], ah, BL[0], BL[1]);
                mma_bf16(oacc[2 * dtp], al, BH[0], BH[1]);
                mma_bf16(oacc[2 * dtp + 1], ah, BH[2], BH[3]);
                mma_bf16(oacc[2 * dtp + 1], ah, BL[2], BL[3]);
                mma_bf16(oacc[2 * dtp + 1], al, BH[2], BH[3]);
            }
        }
    }

    float inv1 = 1.0f / li1, inv2 = 1.0f / li2;
    int i1 = q0 + warp * 16 + r1;
    int i2 = i1 + 8;
    size_t o1 = ((size_t)(b * LL) + i1) * DD + (h << 6) + cq * 2;
    size_t o2 = ((size_t)(b * LL) + i2) * DD + (h << 6) + cq * 2;
#pragma unroll
    for (int dt = 0; dt < 8; dt++) {
        unsigned hi, lo;
        packsplit(oacc[dt][0] * inv1, oacc[dt][1] * inv1, hi, lo);
        *(unsigned*)&Ohi[o1 + dt * 8] = hi;
        *(unsigned*)&Olo[o1 + dt * 8] = lo;
        packsplit(oacc[dt][2] * inv2, oacc[dt][3] * inv2, hi, lo);
        *(unsigned*)&Ohi[o2 + dt * 8] = hi;
        *(unsigned*)&Olo[o2 + dt * 8] = lo;
    }
}

// ---------------- launch ------------------------------------------------------
extern "C" void kernel_launch(void* const* d_in, const int* in_sizes, int n_in,
                              void* d_out, int out_size) {
    const float* src[3] = {0, 0, 0};
    const float* Wmat[4] = {0, 0, 0, 0};
    const float* invf = 0;
    const void* cand8k[2] = {0, 0};
    int nsrc = 0, nw = 0, nc = 0;
    for (int i = 0; i < n_in; i++) {
        int sz = in_sizes[i];
        if (sz == BB * SS * DD && nsrc < 3) src[nsrc++] = (const float*)d_in[i];
        else if (sz == DD * DD && nw < 4) Wmat[nw++] = (const float*)d_in[i];
        else if (sz == 32) invf = (const float*)d_in[i];
        else if (sz == BB * SS && nc < 2) cand8k[nc++] = d_in[i];
    }
    if (nc == 1) cand8k[1] = cand8k[0];
    float* out = (float*)d_out;

    int *pIdx, *pLen, *pSel, *pDt;
    cudaGetSymbolAddress((void**)&pIdx, g_idx);
    cudaGetSymbolAddress((void**)&pLen, g_len);
    cudaGetSymbolAddress((void**)&pSel, g_masksel);
    cudaGetSymbolAddress((void**)&pDt, g_maskdt);

    __nv_bfloat16 *qh, *ql, *kh, *kl, *vh, *vl;
    __nv_bfloat16 *wqh, *wql, *wkh, *wkl, *wvh, *wvl, *woh, *wol;
    __nv_bfloat16 *ohi, *olo, *qrh, *qrl, *krh, *krl, *vph, *vpl;
    cudaGetSymbolAddress((void**)&qh, g_qh);
    cudaGetSymbolAddress((void**)&ql, g_ql);
    cudaGetSymbolAddress((void**)&kh, g_kh);
    cudaGetSymbolAddress((void**)&kl, g_kl);
    cudaGetSymbolAddress((void**)&vh, g_vh);
    cudaGetSymbolAddress((void**)&vl, g_vl);
    cudaGetSymbolAddress((void**)&wqh, g_wqh);
    cudaGetSymbolAddress((void**)&wql, g_wql);
    cudaGetSymbolAddress((void**)&wkh, g_wkh);
    cudaGetSymbolAddress((void**)&wkl, g_wkl);
    cudaGetSymbolAddress((void**)&wvh, g_wvh);
    cudaGetSymbolAddress((void**)&wvl, g_wvl);
    cudaGetSymbolAddress((void**)&woh, g_woh);
    cudaGetSymbolAddress((void**)&wol, g_wol);
    cudaGetSymbolAddress((void**)&ohi, g_Ohi);
    cudaGetSymbolAddress((void**)&olo, g_Olo);
    cudaGetSymbolAddress((void**)&qrh, g_Qrh);
    cudaGetSymbolAddress((void**)&qrl, g_Qrl);
    cudaGetSymbolAddress((void**)&krh, g_Krh);
    cudaGetSymbolAddress((void**)&krl, g_Krl);
    cudaGetSymbolAddress((void**)&vph, g_Vph);
    cudaGetSymbolAddress((void**)&vpl, g_Vpl);

    cudaFuncSetAttribute(flashmma_kernel, cudaFuncAttributeMaxDynamicSharedMemorySize,
                         FT_SMEM);
    cudaFuncSetAttribute(bgemm_kernel<0>, cudaFuncAttributeMaxDynamicSharedMemorySize,
                         GSMEM_BYTES);
    cudaFuncSetAttribute(bgemm_kernel<1>, cudaFuncAttributeMaxDynamicSharedMemorySize,
                         GSMEM_BYTES);
    cudaFuncSetAttribute(bgemm_kernel<2>, cudaFuncAttributeMaxDynamicSharedMemorySize,
                         GSMEM_BYTES);
    cudaFuncSetAttribute(bgemm_kernel<3>, cudaFuncAttributeMaxDynamicSharedMemorySize,
                         GSMEM_BYTES);

    // streams/events for capture-safe fork-join (created once, reused)
    static cudaStream_t st1 = 0, st2 = 0;
    static cudaEvent_t evR = 0, ev1 = 0, ev2 = 0, evFA = 0, evOA = 0;
    if (!st1) {
        cudaStreamCreateWithFlags(&st1, cudaStreamNonBlocking);
        cudaStreamCreateWithFlags(&st2, cudaStreamNonBlocking);
        cudaEventCreateWithFlags(&evR, cudaEventDisableTiming);
        cudaEventCreateWithFlags(&ev1, cudaEventDisableTiming);
        cudaEventCreateWithFlags(&ev2, cudaEventDisableTiming);
        cudaEventCreateWithFlags(&evFA, cudaEventDisableTiming);
        cudaEventCreateWithFlags(&evOA, cudaEventDisableTiming);
    }

    const int n4s = BB * SS * DD / 4, n4w = DD * DD / 4;

    cudaEventRecord(evR, 0);
    cudaStreamWaitEvent(st1, evR, 0);
    cudaStreamWaitEvent(st2, evR, 0);

    // ---- stream 1: K chain (fused RoPE; no idx dependency) ----
    split_kernel<<<(n4s + 255) / 256, 256, 0, st1>>>((const float4*)src[1], (uint2*)kh,
                                                     (uint2*)kl, n4s);
    split_kernel<<<(n4w + 255) / 256, 256, 0, st1>>>((const float4*)Wmat[1], (uint2*)wkh,
                                                     (uint2*)wkl, n4w);
    bgemm_kernel<1><<<dim3((BB * SS) / GBM, DD / GBN), 256, GSMEM_BYTES, st1>>>(
        kh, kl, wkh, wkl, 0, krh, krl, pIdx, pLen, invf, -1);
    cudaEventRecord(ev1, st1);

    // ---- stream 0: mask detect/compact (gates only Q gather), then Q chain ----
    detect_mask_kernel<<<1, 256>>>(cand8k[0], cand8k[1], pSel, pDt);
    compact_kernel<<<BB, 32>>>(cand8k[0], cand8k[1], pSel, pDt, pIdx, pLen);
    split_kernel<<<(n4s + 255) / 256, 256>>>((const float4*)src[0], (uint2*)qh,
                                             (uint2*)ql, n4s);
    split_kernel<<<(n4w + 255) / 256, 256>>>((const float4*)Wmat[0], (uint2*)wqh,
                                             (uint2*)wql, n4w);
    bgemm_kernel<0><<<dim3((BB * LL) / GBM, DD / GBN), 256, GSMEM_BYTES>>>(
        qh, ql, wqh, wql, 0, qrh, qrl, pIdx, pLen, invf, -1);

    // ---- stream 2: V chain (+Wo split; no idx dependency) ----
    split_kernel<<<(n4s + 255) / 256, 256, 0, st2>>>((const float4*)src[2], (uint2*)vh,
                                                     (uint2*)vl, n4s);
    split_kernel<<<(n4w + 255) / 256, 256, 0, st2>>>((const float4*)Wmat[2], (uint2*)wvh,
                                                     (uint2*)wvl, n4w);
    split_kernel<<<(n4w + 255) / 256, 256, 0, st2>>>((const float4*)Wmat[3], (uint2*)woh,
                                                     (uint2*)wol, n4w);
    bgemm_kernel<3><<<dim3((BB * SS) / GBM, DD / GBN), 256, GSMEM_BYTES, st2>>>(
        vh, vl, wvh, wvl, 0, vph, vpl, pIdx, pLen, invf, -1);
    cudaEventRecord(ev2, st2);

    // ---- join on stream 0; flashA (light half: q-tiles 0..11) ----
    cudaStreamWaitEvent(0, ev1, 0);
    cudaStreamWaitEvent(0, ev2, 0);
    flashmma_kernel<<<dim3(BB * HH, 12), 128, FT_SMEM>>>(
        qrh, qrl, krh, krl, vph, vpl, ohi, olo, pIdx, pLen, 0);
    cudaEventRecord(evFA, 0);

    // ---- flashB (heavy half) on stream 0; OprojA overlaps it on stream 2 ----
    flashmma_kernel<<<dim3(BB * HH, 12), 128, FT_SMEM>>>(
        qrh, qrl, krh, krl, vph, vpl, ohi, olo, pIdx, pLen, 12);

    cudaStreamWaitEvent(st2, evFA, 0);
    bgemm_kernel<2><<<dim3(24, DD / GBN), 256, GSMEM_BYTES, st2>>>(
        ohi, olo, woh, wol, out, 0, 0, pIdx, pLen, invf, 0);
    cudaEventRecord(evOA, st2);

    // ---- OprojB on stream 0 after flashB; rejoin OprojA ----
    bgemm_kernel<2><<<dim3(24, DD / GBN), 256, GSMEM_BYTES>>>(
        ohi, olo, woh, wol, out, 0, 0, pIdx, pLen, invf, 1);
    cudaStreamWaitEvent(0, evOA, 0);
}

// round 14
// speedup vs baseline: 1.1457x; 1.1457x over previous
#include <cuda_runtime.h>
#include <cuda_bf16.h>
#include <math.h>

// Problem constants (fixed shapes)
#define BB 4
#define SS 2048
#define DD 1024
#define HH 16
#define DH 64
#define LL 1536

// ---------------- scratch (device globals; no allocations allowed) ----------
__device__ int   g_idx[BB * LL];           // kept indices per batch
__device__ int   g_len[BB];                // kept lengths

// bf16 split copies (hi + lo, x = hi + lo to ~2^-17)
__device__ __nv_bfloat16 g_qh[BB * SS * DD], g_ql[BB * SS * DD];
__device__ __nv_bfloat16 g_kh[BB * SS * DD], g_kl[BB * SS * DD];
__device__ __nv_bfloat16 g_vh[BB * SS * DD], g_vl[BB * SS * DD];
__device__ __nv_bfloat16 g_wqh[DD * DD], g_wql[DD * DD];
__device__ __nv_bfloat16 g_wkh[DD * DD], g_wkl[DD * DD];
__device__ __nv_bfloat16 g_wvh[DD * DD], g_wvl[DD * DD];
__device__ __nv_bfloat16 g_woh[DD * DD], g_wol[DD * DD];
__device__ __nv_bfloat16 g_Ohi[BB * LL * DD], g_Olo[BB * LL * DD];  // flash out
// RoPE'd attention operands + projected V, split bf16
__device__ __nv_bfloat16 g_Qrh[BB * HH * LL * DH], g_Qrl[BB * HH * LL * DH];
__device__ __nv_bfloat16 g_Krh[BB * HH * SS * DH], g_Krl[BB * HH * SS * DH];
__device__ __nv_bfloat16 g_Vph[BB * HH * SS * DH], g_Vpl[BB * HH * SS * DH];

// ---------------- helpers -----------------------------------------------------
__device__ __forceinline__ unsigned s2u(const void* p) {
    return (unsigned)__cvta_generic_to_shared(p);
}
__device__ __forceinline__ void cpa16(unsigned dst, const void* src) {
    asm volatile("cp.async.cg.shared.global [%0], [%1], 16;\n" :: "r"(dst), "l"(src));
}
__device__ __forceinline__ void cpa_commit() {
    asm volatile("cp.async.commit_group;\n");
}
__device__ __forceinline__ void cpa_wait0() {
    asm volatile("cp.async.wait_group 0;\n");
}
__device__ __forceinline__ float ex2f(float x) {
    float y;
    asm("ex2.approx.f32 %0, %1;" : "=f"(y) : "f"(x));
    return y;
}
__device__ __forceinline__ void packsplit(float x, float y, unsigned& hi, unsigned& lo) {
    union { __nv_bfloat16 h[2]; unsigned u; } H, L;
    __nv_bfloat16 hx = __float2bfloat16(x), hy = __float2bfloat16(y);
    H.h[0] = hx;
    H.h[1] = hy;
    L.h[0] = __float2bfloat16(x - __bfloat162float(hx));
    L.h[1] = __float2bfloat16(y - __bfloat162float(hy));
    hi = H.u;
    lo = L.u;
}
__device__ __forceinline__ void mma_bf16(float* d, const unsigned* a,
                                         unsigned b0, unsigned b1) {
    asm volatile(
        "mma.sync.aligned.m16n8k16.row.col.f32.bf16.bf16.f32 "
        "{%0,%1,%2,%3}, {%4,%5,%6,%7}, {%8,%9}, {%0,%1,%2,%3};\n"
        : "+f"(d[0]), "+f"(d[1]), "+f"(d[2]), "+f"(d[3])
        : "r"(a[0]), "r"(a[1]), "r"(a[2]), "r"(a[3]), "r"(b0), "r"(b1));
}
__device__ __forceinline__ void ldm4(unsigned* r, unsigned a) {
    asm volatile("ldmatrix.sync.aligned.m8n8.x4.shared.b16 {%0,%1,%2,%3}, [%4];\n"
                 : "=r"(r[0]), "=r"(r[1]), "=r"(r[2]), "=r"(r[3]) : "r"(a));
}
__device__ __forceinline__ void ldm4t(unsigned* r, unsigned a) {
    asm volatile("ldmatrix.sync.aligned.m8n8.x4.trans.shared.b16 {%0,%1,%2,%3}, [%4];\n"
                 : "=r"(r[0]), "=r"(r[1]), "=r"(r[2]), "=r"(r[3]) : "r"(a));
}

// ---------------- 1) ragged compaction with inline dtype detection ----------
// Each block classifies the two 8192-elem candidates (first 2048 words) and
// then compacts its batch row. Classification: i32-bool / f32-bool / u8-bool;
// positions (arange) fails all three (value 2 appears in every row).
__global__ void compact_kernel(const void* candA, const void* candB,
                               int* __restrict__ idxb, int* __restrict__ lenb) {
    int b = blockIdx.x;
    int lane = threadIdx.x;  // 32 threads

    unsigned badA = 0, badB = 0;  // bit0: u8, bit1: i32, bit2: f32
    for (int c = 0; c < 2; c++) {
        const unsigned* p = (const unsigned*)(c ? candB : candA);
        unsigned bad = 0;
        for (int i = lane; i < 2048; i += 32) {
            unsigned v = p[i];
            if ((v | (v >> 8) | (v >> 16) | (v >> 24)) & 0xFEu) bad |= 1u;
            if (v > 1u) bad |= 2u;
            if (v != 0u && v != 0x3F800000u) bad |= 4u;
        }
        for (int o = 16; o > 0; o >>= 1)
            bad |= __shfl_xor_sync(0xffffffffu, bad, o);
        if (c) badB = bad; else badA = bad;
    }
    // pick mask candidate + dtype (same priority order as before)
    const void* mp;
    int wide;
    if (!(badA & 2u))      { mp = candA; wide = 1; }
    else if (!(badA & 4u)) { mp = candA; wide = 1; }
    else if (!(badA & 1u)) { mp = candA; wide = 0; }
    else if (!(badB & 2u)) { mp = candB; wide = 1; }
    else if (!(badB & 4u)) { mp = candB; wide = 1; }
    else                   { mp = candB; wide = !(badB & 1u) ? 0 : 0; }

    int base = lane * 64;
    int kept[64];
    int cnt = 0;
    if (wide) {
        const unsigned* sp = (const unsigned*)mp + b * SS;
        for (int t = 0; t < 64; t++) { kept[t] = (sp[base + t] != 0u); cnt += kept[t]; }
    } else {
        const unsigned char* sp = (const unsigned char*)mp + b * SS;
        for (int t = 0; t < 64; t++) { kept[t] = (sp[base + t] != 0); cnt += kept[t]; }
    }

    int inc = cnt;
    for (int o = 1; o < 32; o <<= 1) {
        int v = __shfl_up_sync(0xffffffffu, inc, o);
        if (lane >= o) inc += v;
    }
    int off = inc - cnt;
    int total = __shfl_sync(0xffffffffu, inc, 31);
    for (int t = 0; t < 64; t++) {
        if (kept[t]) {
            if (off < LL) idxb[b * LL + off] = base + t;
            off++;
        }
    }
    int tot = min(total, LL);
    if (lane == 0) lenb[b] = tot;
    for (int i = tot + lane; i < LL; i += 32) idxb[b * LL + i] = 0;
}

// ---------------- 1b) fp32 -> bf16 hi/lo split --------------------------------
__global__ void split_kernel(const float4* __restrict__ in, uint2* __restrict__ hi,
                             uint2* __restrict__ lo, int n4) {
    int i = blockIdx.x * 256 + threadIdx.x;
    if (i >= n4) return;
    float4 v = in[i];
    union { __nv_bfloat16 b4[4]; uint2 u; } H, L;
    float vv[4] = {v.x, v.y, v.z, v.w};
#pragma unroll
    for (int k = 0; k < 4; k++) {
        __nv_bfloat16 h = __float2bfloat16(vv[k]);
        H.b4[k] = h;
        L.b4[k] = __float2bfloat16(vv[k] - __bfloat162float(h));
    }
    hi[i] = H.u;
    lo[i] = L.u;
}

// ---------------- 2) split-bf16 tensor-core GEMM ------------------------------
// C = A * W^T. Tile 128x128, BK=32, 256 threads (8 warps), warp tile 32x64.
// MODE 0: Q proj + fused RoPE -> split bf16 [b,h,i,dh]; skip invalid tiles
// MODE 1: K proj + fused RoPE -> split bf16 [b,h,s,dh]
// MODE 2: O proj (direct; store fp32 to out, zero invalid rows; skip->zeros)
// MODE 3: V proj (direct rows; scatter split bf16 [b,h,s,dh])
#define GBM 128
#define GBN 128
#define GBK 32
#define SAW 40  // smem row stride in bf16 elems (80B: 16B-aligned, conflict-free)
#define MAT_ELEMS (128 * SAW)
#define MAT_BYTES (MAT_ELEMS * 2)
#define GSMEM_BYTES (2 * 4 * MAT_BYTES + 768)
#define QSCALE 0.18033688011112042f

template <int MODE>
__global__ void __launch_bounds__(256, 2) bgemm_kernel(
    const __nv_bfloat16* __restrict__ Ahi, const __nv_bfloat16* __restrict__ Alo,
    const __nv_bfloat16* __restrict__ Bhi, const __nv_bfloat16* __restrict__ Blo,
    float* __restrict__ C,
    __nv_bfloat16* __restrict__ Chi, __nv_bfloat16* __restrict__ Clo,
    const int* __restrict__ idxb, const int* __restrict__ lenb,
    const float* __restrict__ invf) {
    extern __shared__ char sm[];
    // layout per buf: AH, AL, BH, BL each MAT_BYTES
    __nv_bfloat16* base0 = (__nv_bfloat16*)sm;
    int* rowSrc = (int*)(sm + 2 * 4 * MAT_BYTES);

    int tid = threadIdx.x;
    int m0 = blockIdx.x * GBM;
    int n0 = blockIdx.y * GBN;

    // Tile skip: tiles never span batches for MODE 0/2 (LL % GBM == 0).
    if (MODE == 0 || MODE == 2) {
        int b = m0 / LL;
        if ((m0 - b * LL) >= lenb[b]) {
            if (MODE == 2) {
                for (int t = tid; t < GBM * GBN / 4; t += 256) {
                    int r = t >> 5, c4 = t & 31;
                    *(float4*)&C[(size_t)(m0 + r) * DD + n0 + c4 * 4] =
                        make_float4(0.f, 0.f, 0.f, 0.f);
                }
            }
            return;
        }
    }

    for (int r = tid; r < GBM; r += 256) {
        int m = m0 + r;
        int src;
        if (MODE == 0) {
            int b = m / LL, i = m - b * LL;
            int len = lenb[b];
            int iv = (i < len) ? idxb[b * LL + i] : 0;
            src = b * SS + iv;
        } else {
            src = m;
        }
        rowSrc[r] = src;
    }
    __syncthreads();

    auto issue = [&](int buf, int kt) {
        __nv_bfloat16* aH = base0 + buf * 4 * MAT_ELEMS;
        __nv_bfloat16* aL = aH + MAT_ELEMS;
        __nv_bfloat16* bH = aL + MAT_ELEMS;
        __nv_bfloat16* bL = bH + MAT_ELEMS;
#pragma unroll
        for (int it = 0; it < 2; it++) {
            int ca = tid + it * 256;          // 0..511: row=ca>>2, 16B chunk=ca&3
            int row = ca >> 2, ch = ca & 3;
            size_t soA = (size_t)rowSrc[row] * DD + kt + ch * 8;
            cpa16(s2u(&aH[row * SAW + ch * 8]), Ahi + soA);
            cpa16(s2u(&aL[row * SAW + ch * 8]), Alo + soA);
            size_t soB = (size_t)(n0 + row) * DD + kt + ch * 8;
            cpa16(s2u(&bH[row * SAW + ch * 8]), Bhi + soB);
            cpa16(s2u(&bL[row * SAW + ch * 8]), Blo + soB);
        }
        cpa_commit();
    };

    float acc[2][8][4];
#pragma unroll
    for (int mt = 0; mt < 2; mt++)
#pragma unroll
        for (int nt = 0; nt < 8; nt++)
#pragma unroll
            for (int k = 0; k < 4; k++) acc[mt][nt][k] = 0.f;

    int lane = tid & 31, warp = tid >> 5;
    int wm = (warp & 3) * 32, wn = (warp >> 2) * 64;
    int grp = lane >> 3, gr = lane & 7;

    issue(0, 0);

    const int NK = DD / GBK;  // 32
    for (int s = 0; s < NK; s++) {
        cpa_wait0();
        __syncthreads();
        if (s + 1 < NK) issue((s + 1) & 1, (s + 1) * GBK);

        int buf = s & 1;
        unsigned aHb = s2u(base0 + buf * 4 * MAT_ELEMS);
        unsigned aLb = aHb + MAT_BYTES;
        unsigned bHb = aLb + MAT_BYTES;
        unsigned bLb = bHb + MAT_BYTES;

#pragma unroll
        for (int ks = 0; ks < 2; ks++) {
            int k = ks * 16;
            unsigned AH[2][4], AL[2][4];
#pragma unroll
            for (int mt = 0; mt < 2; mt++) {
                unsigned off = ((wm + mt * 16 + (lane & 15)) * SAW + k +
                                (lane >> 4) * 8) * 2;
                ldm4(AH[mt], aHb + off);
                ldm4(AL[mt], aLb + off);
            }
#pragma unroll
            for (int half = 0; half < 4; half++) {
                unsigned ad = ((wn + half * 16 + ((grp & 2) << 2) + gr) * SAW + k +
                               (grp & 1) * 8) * 2;
                unsigned tH[4], tL[4];
                ldm4(tH, bHb + ad);
                ldm4(tL, bLb + ad);
#pragma unroll
                for (int mt = 0; mt < 2; mt++) {
                    mma_bf16(acc[mt][2 * half], AH[mt], tH[0], tH[1]);
                    mma_bf16(acc[mt][2 * half], AH[mt], tL[0], tL[1]);
                    mma_bf16(acc[mt][2 * half], AL[mt], tH[0], tH[1]);
                    mma_bf16(acc[mt][2 * half + 1], AH[mt], tH[2], tH[3]);
                    mma_bf16(acc[mt][2 * half + 1], AH[mt], tL[2], tL[3]);
                    mma_bf16(acc[mt][2 * half + 1], AL[mt], tH[2], tH[3]);
                }
            }
        }
    }

    int r = lane >> 2, c2 = (lane & 3) * 2;

    if (MODE == 0 || MODE == 1) {
        // Fused RoPE epilogue. Warp tile = 64 cols = one head; column dh pairs
        // with dh+32 held by the SAME thread (nt and nt+4).
        int h = (n0 + wn) >> 6;
#pragma unroll
        for (int mt = 0; mt < 2; mt++)
#pragma unroll
            for (int half = 0; half < 2; half++) {
                int m = m0 + wm + mt * 16 + r + half * 8;
                int pos;
                size_t obase;
                if (MODE == 0) {
                    int b = m / LL, i = m - b * LL;
                    pos = rowSrc[m - m0] - b * SS;
                    obase = ((size_t)(b * HH + h) * LL + i) * DH;
                } else {
                    int b = m >> 11, ss = m & (SS - 1);
                    pos = ss;
                    obase = ((size_t)(b * HH + h) * SS + ss) * DH;
                }
                float fp = (float)pos;
#pragma unroll
                for (int nt = 0; nt < 4; nt++) {
                    int dh = nt * 8 + c2;
                    float s0, c0, s1, c1;
                    sincosf(fp * invf[dh], &s0, &c0);
                    sincosf(fp * invf[dh + 1], &s1, &c1);
                    float x1a = acc[mt][nt][half * 2 + 0];
                    float x1b = acc[mt][nt][half * 2 + 1];
                    float x2a = acc[mt][nt + 4][half * 2 + 0];
                    float x2b = acc[mt][nt + 4][half * 2 + 1];
                    float o1a = x1a * c0 - x2a * s0;
                    float o2a = x2a * c0 + x1a * s0;
                    float o1b = x1b * c1 - x2b * s1;
                    float o2b = x2b * c1 + x1b * s1;
                    if (MODE == 0) {
                        o1a *= QSCALE; o1b *= QSCALE;
                        o2a *= QSCALE; o2b *= QSCALE;
                    }
                    unsigned hi, lo;
                    packsplit(o1a, o1b, hi, lo);
                    *(unsigned*)&Chi[obase + dh] = hi;
                    *(unsigned*)&Clo[obase + dh] = lo;
                    packsplit(o2a, o2b, hi, lo);
                    *(unsigned*)&Chi[obase + dh + 32] = hi;
                    *(unsigned*)&Clo[obase + dh + 32] = lo;
                }
            }
        return;
    }

#pragma unroll
    for (int mt = 0; mt < 2; mt++)
#pragma unroll
        for (int nt = 0; nt < 8; nt++) {
            int n = n0 + wn + nt * 8 + c2;
#pragma unroll
            for (int half = 0; half < 2; half++) {
                int m = m0 + wm + mt * 16 + r + half * 8;
                float v0 = acc[mt][nt][half * 2 + 0];
                float v1 = acc[mt][nt][half * 2 + 1];
                if (MODE == 3) {
                    int b = m >> 11, ss = m & (SS - 1);
                    int h = n >> 6, dh = n & 63;
                    unsigned hi, lo;
                    packsplit(v0, v1, hi, lo);
                    size_t o = (((size_t)(b * HH + h) * SS) + ss) * DH + dh;
                    *(unsigned*)&Chi[o] = hi;
                    *(unsigned*)&Clo[o] = lo;
                } else {
                    int b = m / LL, i = m - b * LL;
                    bool valid = (i < lenb[b]);
                    float2 o = valid ? make_float2(v0, v1) : make_float2(0.f, 0.f);
                    *(float2*)&C[(size_t)m * DD + n] = o;
                }
            }
        }
}

// ---------------- 4) flash attention on tensor cores --------------------------
// K/V tiles double-buffered via cp.async. Heavy-first CTA order: blockIdx.y
// reversed so the causally-deep (long) q-tiles launch first; light tiles
// backfill the final wave.
#define FT_PITCH 72
#define FT_TILE (64 * FT_PITCH)
#define FT_SMEM (10 * FT_TILE * 2 + 256)

__global__ void __launch_bounds__(128, 2) flashmma_kernel(
    const __nv_bfloat16* __restrict__ Qh, const __nv_bfloat16* __restrict__ Ql,
    const __nv_bfloat16* __restrict__ Kh, const __nv_bfloat16* __restrict__ Kl,
    const __nv_bfloat16* __restrict__ Vh, const __nv_bfloat16* __restrict__ Vl,
    __nv_bfloat16* __restrict__ Ohi, __nv_bfloat16* __restrict__ Olo,
    const int* __restrict__ idxb, const int* __restrict__ lenb) {
    int bhid = blockIdx.x;
    int b = bhid >> 4, h = bhid & 15;
    int q0 = (gridDim.y - 1 - blockIdx.y) << 6;  // heavy-first
    int len = lenb[b];
    if (q0 >= len) return;

    extern __shared__ __nv_bfloat16 sb[];
    __nv_bfloat16* Qsh = sb;
    __nv_bfloat16* Qsl = Qsh + FT_TILE;
    __nv_bfloat16* KV0 = Qsl + FT_TILE;  // per buf: Ksh,Ksl,Vsh,Vsl
    int* qcap = (int*)(sb + 10 * FT_TILE);

    int tid = threadIdx.x, lane = tid & 31, warp = tid >> 5;
    int grp = lane >> 3, gr = lane & 7;
    const size_t hb = (size_t)(b * HH + h);

    const __nv_bfloat16* Kgh = Kh + hb * SS * DH;
    const __nv_bfloat16* Kgl = Kl + hb * SS * DH;
    const __nv_bfloat16* Vgh = Vh + hb * SS * DH;
    const __nv_bfloat16* Vgl = Vl + hb * SS * DH;

    auto issueKV = [&](int buf, int t) {
        __nv_bfloat16* kH = KV0 + buf * 4 * FT_TILE;
#pragma unroll
        for (int it = 0; it < 4; it++) {
            int ca = tid + it * 128;
            int row = ca >> 3, col = (ca & 7) * 8;
            size_t go = (size_t)(t * 64 + row) * DH + col;
            unsigned so = s2u(kH + row * FT_PITCH + col);
            cpa16(so, Kgh + go);
            cpa16(so + FT_TILE * 2, Kgl + go);
            cpa16(so + FT_TILE * 4, Vgh + go);
            cpa16(so + FT_TILE * 6, Vgl + go);
        }
        cpa_commit();
    };

    const __nv_bfloat16* Qgh = Qh + (hb * LL + q0) * DH;
    const __nv_bfloat16* Qgl = Ql + (hb * LL + q0) * DH;
#pragma unroll
    for (int it = 0; it < 4; it++) {
        int c = tid + it * 128;
        int r = c >> 3, col = (c & 7) * 8;
        *(uint4*)&Qsh[r * FT_PITCH + col] = *(const uint4*)&Qgh[r * DH + col];
        *(uint4*)&Qsl[r * FT_PITCH + col] = *(const uint4*)&Qgl[r * DH + col];
    }
    if (tid < 64) {
        int i = q0 + tid;
        qcap[tid] = (i < len) ? idxb[b * LL + i] : 0;
    }
    issueKV(0, 0);
    __syncthreads();

    int nv = min(64, len - q0);
    int ntiles = (qcap[nv - 1] >> 6) + 1;
    int r1 = lane >> 2, cq = lane & 3;
    int cap1 = qcap[warp * 16 + r1];
    int cap2 = qcap[warp * 16 + r1 + 8];

    // hoist Q fragments
    unsigned qshb = s2u(Qsh), qslb = s2u(Qsl);
    unsigned QH[4][4], QL[4][4];
#pragma unroll
    for (int ks = 0; ks < 4; ks++) {
        unsigned off = ((warp * 16 + (lane & 15)) * FT_PITCH + ks * 16 +
                        (lane >> 4) * 8) * 2;
        ldm4(QH[ks], qshb + off);
        ldm4(QL[ks], qslb + off);
    }

    float mi1 = -1e30f, mi2 = -1e30f, li1 = 0.f, li2 = 0.f;
    float oacc[8][4];
#pragma unroll
    for (int dt = 0; dt < 8; dt++)
#pragma unroll
        for (int k = 0; k < 4; k++) oacc[dt][k] = 0.f;

    for (int t = 0; t < ntiles; t++) {
        cpa_wait0();
        __syncthreads();
        if (t + 1 < ntiles) issueKV((t + 1) & 1, t + 1);

        int buf = t & 1;
        unsigned kshb = s2u(KV0 + buf * 4 * FT_TILE);
        unsigned kslb = kshb + FT_TILE * 2;
        unsigned vshb = kslb + FT_TILE * 2;
        unsigned vslb = vshb + FT_TILE * 2;

        float sacc[8][4];
#pragma unroll
        for (int nt = 0; nt < 8; nt++)
#pragma unroll
            for (int k = 0; k < 4; k++) sacc[nt][k] = 0.f;

#pragma unroll
        for (int ks = 0; ks < 4; ks++) {
            int k = ks * 16;
#pragma unroll
            for (int half = 0; half < 4; half++) {
                unsigned ad = ((half * 16 + ((grp & 2) << 2) + gr) * FT_PITCH + k +
                               (grp & 1) * 8) * 2;
                unsigned tH[4], tL[4];
                ldm4(tH, kshb + ad);
                ldm4(tL, kslb + ad);
                mma_bf16(sacc[2 * half], QH[ks], tH[0], tH[1]);
                mma_bf16(sacc[2 * half], QH[ks], tL[0], tL[1]);
                mma_bf16(sacc[2 * half], QL[ks], tH[0], tH[1]);
                mma_bf16(sacc[2 * half + 1], QH[ks], tH[2], tH[3]);
                mma_bf16(sacc[2 * half + 1], QH[ks], tL[2], tL[3]);
                mma_bf16(sacc[2 * half + 1], QL[ks], tH[2], tH[3]);
            }
        }

        float mn1 = mi1, mn2 = mi2;
#pragma unroll
        for (int nt = 0; nt < 8; nt++) {
            int jg = (t << 6) + nt * 8 + cq * 2;
            sacc[nt][0] = (jg <= cap1) ? sacc[nt][0] : -1e30f;
            sacc[nt][1] = (jg + 1 <= cap1) ? sacc[nt][1] : -1e30f;
            sacc[nt][2] = (jg <= cap2) ? sacc[nt][2] : -1e30f;
            sacc[nt][3] = (jg + 1 <= cap2) ? sacc[nt][3] : -1e30f;
            mn1 = fmaxf(mn1, fmaxf(sacc[nt][0], sacc[nt][1]));
            mn2 = fmaxf(mn2, fmaxf(sacc[nt][2], sacc[nt][3]));
        }
        mn1 = fmaxf(mn1, __shfl_xor_sync(0xffffffffu, mn1, 1));
        mn1 = fmaxf(mn1, __shfl_xor_sync(0xffffffffu, mn1, 2));
        mn2 = fmaxf(mn2, __shfl_xor_sync(0xffffffffu, mn2, 1));
        mn2 = fmaxf(mn2, __shfl_xor_sync(0xffffffffu, mn2, 2));
        float corr1 = ex2f(mi1 - mn1), corr2 = ex2f(mi2 - mn2);
        mi1 = mn1;
        mi2 = mn2;
        float rs1 = 0.f, rs2 = 0.f;
#pragma unroll
        for (int nt = 0; nt < 8; nt++) {
            sacc[nt][0] = ex2f(sacc[nt][0] - mn1);
            sacc[nt][1] = ex2f(sacc[nt][1] - mn1);
            sacc[nt][2] = ex2f(sacc[nt][2] - mn2);
            sacc[nt][3] = ex2f(sacc[nt][3] - mn2);
            rs1 += sacc[nt][0] + sacc[nt][1];
            rs2 += sacc[nt][2] + sacc[nt][3];
        }
        rs1 += __shfl_xor_sync(0xffffffffu, rs1, 1);
        rs1 += __shfl_xor_sync(0xffffffffu, rs1, 2);
        rs2 += __shfl_xor_sync(0xffffffffu, rs2, 1);
        rs2 += __shfl_xor_sync(0xffffffffu, rs2, 2);
        li1 = li1 * corr1 + rs1;
        li2 = li2 * corr2 + rs2;
#pragma unroll
        for (int dt = 0; dt < 8; dt++) {
            oacc[dt][0] *= corr1;
            oacc[dt][1] *= corr1;
            oacc[dt][2] *= corr2;
            oacc[dt][3] *= corr2;
        }

#pragma unroll
        for (int ks = 0; ks < 4; ks++) {
            unsigned ah[4], al[4];
            packsplit(sacc[2 * ks][0], sacc[2 * ks][1], ah[0], al[0]);
            packsplit(sacc[2 * ks][2], sacc[2 * ks][3], ah[1], al[1]);
            packsplit(sacc[2 * ks + 1][0], sacc[2 * ks + 1][1], ah[2], al[2]);
            packsplit(sacc[2 * ks + 1][2], sacc[2 * ks + 1][3], ah[3], al[3]);
#pragma unroll
            for (int dtp = 0; dtp < 4; dtp++) {
                unsigned off = ((ks * 16 + (lane & 15)) * FT_PITCH + dtp * 16 +
                                (lane >> 4) * 8) * 2;
                unsigned BH[4], BL[4];
                ldm4t(BH, vshb + off);
                ldm4t(BL, vslb + off);
                mma_bf16(oacc[2 * dtp], ah, BH[0], BH[1]);
                mma_bf16(oacc[2 * dtp], ah, BL[0], BL[1]);
                mma_bf16(oacc[2 * dtp], al, BH[0], BH[1]);
                mma_bf16(oacc[2 * dtp + 1], ah, BH[2], BH[3]);
                mma_bf16(oacc[2 * dtp + 1], ah, BL[2], BL[3]);
                mma_bf16(oacc[2 * dtp + 1], al, BH[2], BH[3]);
            }
        }
    }

    float inv1 = 1.0f / li1, inv2 = 1.0f / li2;
    int i1 = q0 + warp * 16 + r1;
    int i2 = i1 + 8;
    size_t o1 = ((size_t)(b * LL) + i1) * DD + (h << 6) + cq * 2;
    size_t o2 = ((size_t)(b * LL) + i2) * DD + (h << 6) + cq * 2;
#pragma unroll
    for (int dt = 0; dt < 8; dt++) {
        unsigned hi, lo;
        packsplit(oacc[dt][0] * inv1, oacc[dt][1] * inv1, hi, lo);
        *(unsigned*)&Ohi[o1 + dt * 8] = hi;
        *(unsigned*)&Olo[o1 + dt * 8] = lo;
        packsplit(oacc[dt][2] * inv2, oacc[dt][3] * inv2, hi, lo);
        *(unsigned*)&Ohi[o2 + dt * 8] = hi;
        *(unsigned*)&Olo[o2 + dt * 8] = lo;
    }
}

// ---------------- launch ------------------------------------------------------
extern "C" void kernel_launch(void* const* d_in, const int* in_sizes, int n_in,
                              void* d_out, int out_size) {
    const float* src[3] = {0, 0, 0};
    const float* Wmat[4] = {0, 0, 0, 0};
    const float* invf = 0;
    const void* cand8k[2] = {0, 0};
    int nsrc = 0, nw = 0, nc = 0;
    for (int i = 0; i < n_in; i++) {
        int sz = in_sizes[i];
        if (sz == BB * SS * DD && nsrc < 3) src[nsrc++] = (const float*)d_in[i];
        else if (sz == DD * DD && nw < 4) Wmat[nw++] = (const float*)d_in[i];
        else if (sz == 32) invf = (const float*)d_in[i];
        else if (sz == BB * SS && nc < 2) cand8k[nc++] = d_in[i];
    }
    if (nc == 1) cand8k[1] = cand8k[0];
    float* out = (float*)d_out;

    int *pIdx, *pLen;
    cudaGetSymbolAddress((void**)&pIdx, g_idx);
    cudaGetSymbolAddress((void**)&pLen, g_len);

    __nv_bfloat16 *qh, *ql, *kh, *kl, *vh, *vl;
    __nv_bfloat16 *wqh, *wql, *wkh, *wkl, *wvh, *wvl, *woh, *wol;
    __nv_bfloat16 *ohi, *olo, *qrh, *qrl, *krh, *krl, *vph, *vpl;
    cudaGetSymbolAddress((void**)&qh, g_qh);
    cudaGetSymbolAddress((void**)&ql, g_ql);
    cudaGetSymbolAddress((void**)&kh, g_kh);
    cudaGetSymbolAddress((void**)&kl, g_kl);
    cudaGetSymbolAddress((void**)&vh, g_vh);
    cudaGetSymbolAddress((void**)&vl, g_vl);
    cudaGetSymbolAddress((void**)&wqh, g_wqh);
    cudaGetSymbolAddress((void**)&wql, g_wql);
    cudaGetSymbolAddress((void**)&wkh, g_wkh);
    cudaGetSymbolAddress((void**)&wkl, g_wkl);
    cudaGetSymbolAddress((void**)&wvh, g_wvh);
    cudaGetSymbolAddress((void**)&wvl, g_wvl);
    cudaGetSymbolAddress((void**)&woh, g_woh);
    cudaGetSymbolAddress((void**)&wol, g_wol);
    cudaGetSymbolAddress((void**)&ohi, g_Ohi);
    cudaGetSymbolAddress((void**)&olo, g_Olo);
    cudaGetSymbolAddress((void**)&qrh, g_Qrh);
    cudaGetSymbolAddress((void**)&qrl, g_Qrl);
    cudaGetSymbolAddress((void**)&krh, g_Krh);
    cudaGetSymbolAddress((void**)&krl, g_Krl);
    cudaGetSymbolAddress((void**)&vph, g_Vph);
    cudaGetSymbolAddress((void**)&vpl, g_Vpl);

    cudaFuncSetAttribute(flashmma_kernel, cudaFuncAttributeMaxDynamicSharedMemorySize,
                         FT_SMEM);
    cudaFuncSetAttribute(bgemm_kernel<0>, cudaFuncAttributeMaxDynamicSharedMemorySize,
                         GSMEM_BYTES);
    cudaFuncSetAttribute(bgemm_kernel<1>, cudaFuncAttributeMaxDynamicSharedMemorySize,
                         GSMEM_BYTES);
    cudaFuncSetAttribute(bgemm_kernel<2>, cudaFuncAttributeMaxDynamicSharedMemorySize,
                         GSMEM_BYTES);
    cudaFuncSetAttribute(bgemm_kernel<3>, cudaFuncAttributeMaxDynamicSharedMemorySize,
                         GSMEM_BYTES);

    // streams/events for capture-safe fork-join (created once, reused)
    static cudaStream_t st1 = 0, st2 = 0;
    static cudaEvent_t evR = 0, ev1 = 0, ev2 = 0;
    if (!st1) {
        cudaStreamCreateWithFlags(&st1, cudaStreamNonBlocking);
        cudaStreamCreateWithFlags(&st2, cudaStreamNonBlocking);
        cudaEventCreateWithFlags(&evR, cudaEventDisableTiming);
        cudaEventCreateWithFlags(&ev1, cudaEventDisableTiming);
        cudaEventCreateWithFlags(&ev2, cudaEventDisableTiming);
    }

    const int n4s = BB * SS * DD / 4, n4w = DD * DD / 4;

    cudaEventRecord(evR, 0);
    cudaStreamWaitEvent(st1, evR, 0);
    cudaStreamWaitEvent(st2, evR, 0);

    // ---- stream 1: K chain (fused RoPE; no idx dependency) ----
    split_kernel<<<(n4s + 255) / 256, 256, 0, st1>>>((const float4*)src[1], (uint2*)kh,
                                                     (uint2*)kl, n4s);
    split_kernel<<<(n4w + 255) / 256, 256, 0, st1>>>((const float4*)Wmat[1], (uint2*)wkh,
                                                     (uint2*)wkl, n4w);
    bgemm_kernel<1><<<dim3((BB * SS) / GBM, DD / GBN), 256, GSMEM_BYTES, st1>>>(
        kh, kl, wkh, wkl, 0, krh, krl, pIdx, pLen, invf);
    cudaEventRecord(ev1, st1);

    // ---- stream 0: compact (with inline mask detect), then Q chain ----
    compact_kernel<<<BB, 32>>>(cand8k[0], cand8k[1], pIdx, pLen);
    split_kernel<<<(n4s + 255) / 256, 256>>>((const float4*)src[0], (uint2*)qh,
                                             (uint2*)ql, n4s);
    split_kernel<<<(n4w + 255) / 256, 256>>>((const float4*)Wmat[0], (uint2*)wqh,
                                             (uint2*)wql, n4w);
    bgemm_kernel<0><<<dim3((BB * LL) / GBM, DD / GBN), 256, GSMEM_BYTES>>>(
        qh, ql, wqh, wql, 0, qrh, qrl, pIdx, pLen, invf);

    // ---- stream 2: V chain (+Wo split; no idx dependency) ----
    split_kernel<<<(n4s + 255) / 256, 256, 0, st2>>>((const float4*)src[2], (uint2*)vh,
                                                     (uint2*)vl, n4s);
    split_kernel<<<(n4w + 255) / 256, 256, 0, st2>>>((const float4*)Wmat[2], (uint2*)wvh,
                                                     (uint2*)wvl, n4w);
    split_kernel<<<(n4w + 255) / 256, 256, 0, st2>>>((const float4*)Wmat[3], (uint2*)woh,
                                                     (uint2*)wol, n4w);
    bgemm_kernel<3><<<dim3((BB * SS) / GBM, DD / GBN), 256, GSMEM_BYTES, st2>>>(
        vh, vl, wvh, wvl, 0, vph, vpl, pIdx, pLen, invf);
    cudaEventRecord(ev2, st2);

    // ---- join, single flash (heavy-first order), single O-proj ----
    cudaStreamWaitEvent(0, ev1, 0);
    cudaStreamWaitEvent(0, ev2, 0);

    flashmma_kernel<<<dim3(BB * HH, LL / 64), 128, FT_SMEM>>>(
        qrh, qrl, krh, krl, vph, vpl, ohi, olo, pIdx, pLen);

    bgemm_kernel<2><<<dim3((BB * LL) / GBM, DD / GBN), 256, GSMEM_BYTES>>>(
        ohi, olo, woh, wol, out, 0, 0, pIdx, pLen, invf);
}

// round 15
// speedup vs baseline: 1.1472x; 1.0013x over previous
#include <cuda_runtime.h>
#include <cuda_bf16.h>
#include <math.h>

// Problem constants (fixed shapes)
#define BB 4
#define SS 2048
#define DD 1024
#define HH 16
#define DH 64
#define LL 1536

// ---------------- scratch (device globals; no allocations allowed) ----------
__device__ int   g_idx[BB * LL];           // kept indices per batch
__device__ int   g_len[BB];                // kept lengths

// bf16 split copies (hi + lo, x = hi + lo to ~2^-17)
__device__ __nv_bfloat16 g_qh[BB * SS * DD], g_ql[BB * SS * DD];
__device__ __nv_bfloat16 g_kh[BB * SS * DD], g_kl[BB * SS * DD];
__device__ __nv_bfloat16 g_vh[BB * SS * DD], g_vl[BB * SS * DD];
__device__ __nv_bfloat16 g_wqh[DD * DD], g_wql[DD * DD];
__device__ __nv_bfloat16 g_wkh[DD * DD], g_wkl[DD * DD];
__device__ __nv_bfloat16 g_wvh[DD * DD], g_wvl[DD * DD];
__device__ __nv_bfloat16 g_woh[DD * DD], g_wol[DD * DD];
__device__ __nv_bfloat16 g_Ohi[BB * LL * DD], g_Olo[BB * LL * DD];  // flash out
// RoPE'd attention operands + projected V, split bf16
__device__ __nv_bfloat16 g_Qrh[BB * HH * LL * DH], g_Qrl[BB * HH * LL * DH];
__device__ __nv_bfloat16 g_Krh[BB * HH * SS * DH], g_Krl[BB * HH * SS * DH];
__device__ __nv_bfloat16 g_Vph[BB * HH * SS * DH], g_Vpl[BB * HH * SS * DH];

// ---------------- helpers -----------------------------------------------------
__device__ __forceinline__ unsigned s2u(const void* p) {
    return (unsigned)__cvta_generic_to_shared(p);
}
__device__ __forceinline__ void cpa16(unsigned dst, const void* src) {
    asm volatile("cp.async.cg.shared.global [%0], [%1], 16;\n" :: "r"(dst), "l"(src));
}
__device__ __forceinline__ void cpa_commit() {
    asm volatile("cp.async.commit_group;\n");
}
__device__ __forceinline__ void cpa_wait0() {
    asm volatile("cp.async.wait_group 0;\n");
}
__device__ __forceinline__ float ex2f(float x) {
    float y;
    asm("ex2.approx.f32 %0, %1;" : "=f"(y) : "f"(x));
    return y;
}
__device__ __forceinline__ void packsplit(float x, float y, unsigned& hi, unsigned& lo) {
    union { __nv_bfloat16 h[2]; unsigned u; } H, L;
    __nv_bfloat16 hx = __float2bfloat16(x), hy = __float2bfloat16(y);
    H.h[0] = hx;
    H.h[1] = hy;
    L.h[0] = __float2bfloat16(x - __bfloat162float(hx));
    L.h[1] = __float2bfloat16(y - __bfloat162float(hy));
    hi = H.u;
    lo = L.u;
}
__device__ __forceinline__ void mma_bf16(float* d, const unsigned* a,
                                         unsigned b0, unsigned b1) {
    asm volatile(
        "mma.sync.aligned.m16n8k16.row.col.f32.bf16.bf16.f32 "
        "{%0,%1,%2,%3}, {%4,%5,%6,%7}, {%8,%9}, {%0,%1,%2,%3};\n"
        : "+f"(d[0]), "+f"(d[1]), "+f"(d[2]), "+f"(d[3])
        : "r"(a[0]), "r"(a[1]), "r"(a[2]), "r"(a[3]), "r"(b0), "r"(b1));
}
__device__ __forceinline__ void ldm4(unsigned* r, unsigned a) {
    asm volatile("ldmatrix.sync.aligned.m8n8.x4.shared.b16 {%0,%1,%2,%3}, [%4];\n"
                 : "=r"(r[0]), "=r"(r[1]), "=r"(r[2]), "=r"(r[3]) : "r"(a));
}
__device__ __forceinline__ void ldm4t(unsigned* r, unsigned a) {
    asm volatile("ldmatrix.sync.aligned.m8n8.x4.trans.shared.b16 {%0,%1,%2,%3}, [%4];\n"
                 : "=r"(r[0]), "=r"(r[1]), "=r"(r[2]), "=r"(r[3]) : "r"(a));
}

// ---------------- 1) ragged compaction with inline dtype detection ----------
// Classification needs only the first 64 words: positions (arange) fails all
// three bool-dtype tests by word 2 (value 2), while the true mask passes on
// any prefix. i32-bool / f32-bool / u8-bool, same priority order as before.
__global__ void compact_kernel(const void* candA, const void* candB,
                               int* __restrict__ idxb, int* __restrict__ lenb) {
    int b = blockIdx.x;
    int lane = threadIdx.x;  // 32 threads

    unsigned badA = 0, badB = 0;  // bit0: u8, bit1: i32, bit2: f32
    for (int c = 0; c < 2; c++) {
        const unsigned* p = (const unsigned*)(c ? candB : candA);
        unsigned bad = 0;
#pragma unroll
        for (int it = 0; it < 2; it++) {
            unsigned v = p[lane + it * 32];
            if ((v | (v >> 8) | (v >> 16) | (v >> 24)) & 0xFEu) bad |= 1u;
            if (v > 1u) bad |= 2u;
            if (v != 0u && v != 0x3F800000u) bad |= 4u;
        }
        for (int o = 16; o > 0; o >>= 1)
            bad |= __shfl_xor_sync(0xffffffffu, bad, o);
        if (c) badB = bad; else badA = bad;
    }
    const void* mp;
    int wide;
    if (!(badA & 2u))      { mp = candA; wide = 1; }
    else if (!(badA & 4u)) { mp = candA; wide = 1; }
    else if (!(badA & 1u)) { mp = candA; wide = 0; }
    else if (!(badB & 2u)) { mp = candB; wide = 1; }
    else if (!(badB & 4u)) { mp = candB; wide = 1; }
    else                   { mp = candB; wide = 0; }

    int base = lane * 64;
    int kept[64];
    int cnt = 0;
    if (wide) {
        const unsigned* sp = (const unsigned*)mp + b * SS;
        for (int t = 0; t < 64; t++) { kept[t] = (sp[base + t] != 0u); cnt += kept[t]; }
    } else {
        const unsigned char* sp = (const unsigned char*)mp + b * SS;
        for (int t = 0; t < 64; t++) { kept[t] = (sp[base + t] != 0); cnt += kept[t]; }
    }

    int inc = cnt;
    for (int o = 1; o < 32; o <<= 1) {
        int v = __shfl_up_sync(0xffffffffu, inc, o);
        if (lane >= o) inc += v;
    }
    int off = inc - cnt;
    int total = __shfl_sync(0xffffffffu, inc, 31);
    for (int t = 0; t < 64; t++) {
        if (kept[t]) {
            if (off < LL) idxb[b * LL + off] = base + t;
            off++;
        }
    }
    int tot = min(total, LL);
    if (lane == 0) lenb[b] = tot;
    for (int i = tot + lane; i < LL; i += 32) idxb[b * LL + i] = 0;
}

// ---------------- 1b) fp32 -> bf16 hi/lo split --------------------------------
__global__ void split_kernel(const float4* __restrict__ in, uint2* __restrict__ hi,
                             uint2* __restrict__ lo, int n4) {
    int i = blockIdx.x * 256 + threadIdx.x;
    if (i >= n4) return;
    float4 v = in[i];
    union { __nv_bfloat16 b4[4]; uint2 u; } H, L;
    float vv[4] = {v.x, v.y, v.z, v.w};
#pragma unroll
    for (int k = 0; k < 4; k++) {
        __nv_bfloat16 h = __float2bfloat16(vv[k]);
        H.b4[k] = h;
        L.b4[k] = __float2bfloat16(vv[k] - __bfloat162float(h));
    }
    hi[i] = H.u;
    lo[i] = L.u;
}

// ---------------- 2) split-bf16 tensor-core GEMM ------------------------------
// C = A * W^T. Tile 128x128, BK=32, 256 threads (8 warps), warp tile 32x64.
// MODE 0: Q proj + fused RoPE -> split bf16 [b,h,i,dh]; skip invalid tiles
// MODE 1: K proj + fused RoPE -> split bf16 [b,h,s,dh]
// MODE 2: O proj (direct; store fp32 to out, zero invalid rows; skip->zeros)
// MODE 3: V proj (direct rows; scatter split bf16 [b,h,s,dh])
#define GBM 128
#define GBN 128
#define GBK 32
#define SAW 40  // smem row stride in bf16 elems (80B: 16B-aligned, conflict-free)
#define MAT_ELEMS (128 * SAW)
#define MAT_BYTES (MAT_ELEMS * 2)
#define GSMEM_BYTES (2 * 4 * MAT_BYTES + 768)
#define QSCALE 0.18033688011112042f

template <int MODE>
__global__ void __launch_bounds__(256, 2) bgemm_kernel(
    const __nv_bfloat16* __restrict__ Ahi, const __nv_bfloat16* __restrict__ Alo,
    const __nv_bfloat16* __restrict__ Bhi, const __nv_bfloat16* __restrict__ Blo,
    float* __restrict__ C,
    __nv_bfloat16* __restrict__ Chi, __nv_bfloat16* __restrict__ Clo,
    const int* __restrict__ idxb, const int* __restrict__ lenb,
    const float* __restrict__ invf) {
    extern __shared__ char sm[];
    // layout per buf: AH, AL, BH, BL each MAT_BYTES
    __nv_bfloat16* base0 = (__nv_bfloat16*)sm;
    int* rowSrc = (int*)(sm + 2 * 4 * MAT_BYTES);

    int tid = threadIdx.x;
    int m0 = blockIdx.x * GBM;
    int n0 = blockIdx.y * GBN;

    // Tile skip: tiles never span batches for MODE 0/2 (LL % GBM == 0).
    if (MODE == 0 || MODE == 2) {
        int b = m0 / LL;
        if ((m0 - b * LL) >= lenb[b]) {
            if (MODE == 2) {
                for (int t = tid; t < GBM * GBN / 4; t += 256) {
                    int r = t >> 5, c4 = t & 31;
                    *(float4*)&C[(size_t)(m0 + r) * DD + n0 + c4 * 4] =
                        make_float4(0.f, 0.f, 0.f, 0.f);
                }
            }
            return;
        }
    }

    for (int r = tid; r < GBM; r += 256) {
        int m = m0 + r;
        int src;
        if (MODE == 0) {
            int b = m / LL, i = m - b * LL;
            int len = lenb[b];
            int iv = (i < len) ? idxb[b * LL + i] : 0;
            src = b * SS + iv;
        } else {
            src = m;
        }
        rowSrc[r] = src;
    }
    __syncthreads();

    auto issue = [&](int buf, int kt) {
        __nv_bfloat16* aH = base0 + buf * 4 * MAT_ELEMS;
        __nv_bfloat16* aL = aH + MAT_ELEMS;
        __nv_bfloat16* bH = aL + MAT_ELEMS;
        __nv_bfloat16* bL = bH + MAT_ELEMS;
#pragma unroll
        for (int it = 0; it < 2; it++) {
            int ca = tid + it * 256;          // 0..511: row=ca>>2, 16B chunk=ca&3
            int row = ca >> 2, ch = ca & 3;
            size_t soA = (size_t)rowSrc[row] * DD + kt + ch * 8;
            cpa16(s2u(&aH[row * SAW + ch * 8]), Ahi + soA);
            cpa16(s2u(&aL[row * SAW + ch * 8]), Alo + soA);
            size_t soB = (size_t)(n0 + row) * DD + kt + ch * 8;
            cpa16(s2u(&bH[row * SAW + ch * 8]), Bhi + soB);
            cpa16(s2u(&bL[row * SAW + ch * 8]), Blo + soB);
        }
        cpa_commit();
    };

    float acc[2][8][4];
#pragma unroll
    for (int mt = 0; mt < 2; mt++)
#pragma unroll
        for (int nt = 0; nt < 8; nt++)
#pragma unroll
            for (int k = 0; k < 4; k++) acc[mt][nt][k] = 0.f;

    int lane = tid & 31, warp = tid >> 5;
    int wm = (warp & 3) * 32, wn = (warp >> 2) * 64;
    int grp = lane >> 3, gr = lane & 7;

    issue(0, 0);

    const int NK = DD / GBK;  // 32
    for (int s = 0; s < NK; s++) {
        cpa_wait0();
        __syncthreads();
        if (s + 1 < NK) issue((s + 1) & 1, (s + 1) * GBK);

        int buf = s & 1;
        unsigned aHb = s2u(base0 + buf * 4 * MAT_ELEMS);
        unsigned aLb = aHb + MAT_BYTES;
        unsigned bHb = aLb + MAT_BYTES;
        unsigned bLb = bHb + MAT_BYTES;

#pragma unroll
        for (int ks = 0; ks < 2; ks++) {
            int k = ks * 16;
            unsigned AH[2][4], AL[2][4];
#pragma unroll
            for (int mt = 0; mt < 2; mt++) {
                unsigned off = ((wm + mt * 16 + (lane & 15)) * SAW + k +
                                (lane >> 4) * 8) * 2;
                ldm4(AH[mt], aHb + off);
                ldm4(AL[mt], aLb + off);
            }
#pragma unroll
            for (int half = 0; half < 4; half++) {
                unsigned ad = ((wn + half * 16 + ((grp & 2) << 2) + gr) * SAW + k +
                               (grp & 1) * 8) * 2;
                unsigned tH[4], tL[4];
                ldm4(tH, bHb + ad);
                ldm4(tL, bLb + ad);
#pragma unroll
                for (int mt = 0; mt < 2; mt++) {
                    mma_bf16(acc[mt][2 * half], AH[mt], tH[0], tH[1]);
                    mma_bf16(acc[mt][2 * half], AH[mt], tL[0], tL[1]);
                    mma_bf16(acc[mt][2 * half], AL[mt], tH[0], tH[1]);
                    mma_bf16(acc[mt][2 * half + 1], AH[mt], tH[2], tH[3]);
                    mma_bf16(acc[mt][2 * half + 1], AH[mt], tL[2], tL[3]);
                    mma_bf16(acc[mt][2 * half + 1], AL[mt], tH[2], tH[3]);
                }
            }
        }
    }

    int r = lane >> 2, c2 = (lane & 3) * 2;

    if (MODE == 0 || MODE == 1) {
        // Fused RoPE epilogue. Warp tile = 64 cols = one head; column dh pairs
        // with dh+32 held by the SAME thread (nt and nt+4).
        int h = (n0 + wn) >> 6;
#pragma unroll
        for (int mt = 0; mt < 2; mt++)
#pragma unroll
            for (int half = 0; half < 2; half++) {
                int m = m0 + wm + mt * 16 + r + half * 8;
                int pos;
                size_t obase;
                if (MODE == 0) {
                    int b = m / LL, i = m - b * LL;
                    pos = rowSrc[m - m0] - b * SS;
                    obase = ((size_t)(b * HH + h) * LL + i) * DH;
                } else {
                    int b = m >> 11, ss = m & (SS - 1);
                    pos = ss;
                    obase = ((size_t)(b * HH + h) * SS + ss) * DH;
                }
                float fp = (float)pos;
#pragma unroll
                for (int nt = 0; nt < 4; nt++) {
                    int dh = nt * 8 + c2;
                    float s0, c0, s1, c1;
                    sincosf(fp * invf[dh], &s0, &c0);
                    sincosf(fp * invf[dh + 1], &s1, &c1);
                    float x1a = acc[mt][nt][half * 2 + 0];
                    float x1b = acc[mt][nt][half * 2 + 1];
                    float x2a = acc[mt][nt + 4][half * 2 + 0];
                    float x2b = acc[mt][nt + 4][half * 2 + 1];
                    float o1a = x1a * c0 - x2a * s0;
                    float o2a = x2a * c0 + x1a * s0;
                    float o1b = x1b * c1 - x2b * s1;
                    float o2b = x2b * c1 + x1b * s1;
                    if (MODE == 0) {
                        o1a *= QSCALE; o1b *= QSCALE;
                        o2a *= QSCALE; o2b *= QSCALE;
                    }
                    unsigned hi, lo;
                    packsplit(o1a, o1b, hi, lo);
                    *(unsigned*)&Chi[obase + dh] = hi;
                    *(unsigned*)&Clo[obase + dh] = lo;
                    packsplit(o2a, o2b, hi, lo);
                    *(unsigned*)&Chi[obase + dh + 32] = hi;
                    *(unsigned*)&Clo[obase + dh + 32] = lo;
                }
            }
        return;
    }

#pragma unroll
    for (int mt = 0; mt < 2; mt++)
#pragma unroll
        for (int nt = 0; nt < 8; nt++) {
            int n = n0 + wn + nt * 8 + c2;
#pragma unroll
            for (int half = 0; half < 2; half++) {
                int m = m0 + wm + mt * 16 + r + half * 8;
                float v0 = acc[mt][nt][half * 2 + 0];
                float v1 = acc[mt][nt][half * 2 + 1];
                if (MODE == 3) {
                    int b = m >> 11, ss = m & (SS - 1);
                    int h = n >> 6, dh = n & 63;
                    unsigned hi, lo;
                    packsplit(v0, v1, hi, lo);
                    size_t o = (((size_t)(b * HH + h) * SS) + ss) * DH + dh;
                    *(unsigned*)&Chi[o] = hi;
                    *(unsigned*)&Clo[o] = lo;
                } else {
                    int b = m / LL, i = m - b * LL;
                    bool valid = (i < lenb[b]);
                    float2 o = valid ? make_float2(v0, v1) : make_float2(0.f, 0.f);
                    *(float2*)&C[(size_t)m * DD + n] = o;
                }
            }
        }
}

// ---------------- 4) flash attention on tensor cores --------------------------
// K/V tiles double-buffered via cp.async. Heavy-first CTA order: blockIdx.y
// reversed so the causally-deep (long) q-tiles launch first; light tiles
// backfill the final wave.
#define FT_PITCH 72
#define FT_TILE (64 * FT_PITCH)
#define FT_SMEM (10 * FT_TILE * 2 + 256)

__global__ void __launch_bounds__(128, 2) flashmma_kernel(
    const __nv_bfloat16* __restrict__ Qh, const __nv_bfloat16* __restrict__ Ql,
    const __nv_bfloat16* __restrict__ Kh, const __nv_bfloat16* __restrict__ Kl,
    const __nv_bfloat16* __restrict__ Vh, const __nv_bfloat16* __restrict__ Vl,
    __nv_bfloat16* __restrict__ Ohi, __nv_bfloat16* __restrict__ Olo,
    const int* __restrict__ idxb, const int* __restrict__ lenb) {
    int bhid = blockIdx.x;
    int b = bhid >> 4, h = bhid & 15;
    int q0 = (gridDim.y - 1 - blockIdx.y) << 6;  // heavy-first
    int len = lenb[b];
    if (q0 >= len) return;

    extern __shared__ __nv_bfloat16 sb[];
    __nv_bfloat16* Qsh = sb;
    __nv_bfloat16* Qsl = Qsh + FT_TILE;
    __nv_bfloat16* KV0 = Qsl + FT_TILE;  // per buf: Ksh,Ksl,Vsh,Vsl
    int* qcap = (int*)(sb + 10 * FT_TILE);

    int tid = threadIdx.x, lane = tid & 31, warp = tid >> 5;
    int grp = lane >> 3, gr = lane & 7;
    const size_t hb = (size_t)(b * HH + h);

    const __nv_bfloat16* Kgh = Kh + hb * SS * DH;
    const __nv_bfloat16* Kgl = Kl + hb * SS * DH;
    const __nv_bfloat16* Vgh = Vh + hb * SS * DH;
    const __nv_bfloat16* Vgl = Vl + hb * SS * DH;

    auto issueKV = [&](int buf, int t) {
        __nv_bfloat16* kH = KV0 + buf * 4 * FT_TILE;
#pragma unroll
        for (int it = 0; it < 4; it++) {
            int ca = tid + it * 128;
            int row = ca >> 3, col = (ca & 7) * 8;
            size_t go = (size_t)(t * 64 + row) * DH + col;
            unsigned so = s2u(kH + row * FT_PITCH + col);
            cpa16(so, Kgh + go);
            cpa16(so + FT_TILE * 2, Kgl + go);
            cpa16(so + FT_TILE * 4, Vgh + go);
            cpa16(so + FT_TILE * 6, Vgl + go);
        }
        cpa_commit();
    };

    const __nv_bfloat16* Qgh = Qh + (hb * LL + q0) * DH;
    const __nv_bfloat16* Qgl = Ql + (hb * LL + q0) * DH;
#pragma unroll
    for (int it = 0; it < 4; it++) {
        int c = tid + it * 128;
        int r = c >> 3, col = (c & 7) * 8;
        *(uint4*)&Qsh[r * FT_PITCH + col] = *(const uint4*)&Qgh[r * DH + col];
        *(uint4*)&Qsl[r * FT_PITCH + col] = *(const uint4*)&Qgl[r * DH + col];
    }
    if (tid < 64) {
        int i = q0 + tid;
        qcap[tid] = (i < len) ? idxb[b * LL + i] : 0;
    }
    issueKV(0, 0);
    __syncthreads();

    int nv = min(64, len - q0);
    int ntiles = (qcap[nv - 1] >> 6) + 1;
    int r1 = lane >> 2, cq = lane & 3;
    int cap1 = qcap[warp * 16 + r1];
    int cap2 = qcap[warp * 16 + r1 + 8];

    // hoist Q fragments
    unsigned qshb = s2u(Qsh), qslb = s2u(Qsl);
    unsigned QH[4][4], QL[4][4];
#pragma unroll
    for (int ks = 0; ks < 4; ks++) {
        unsigned off = ((warp * 16 + (lane & 15)) * FT_PITCH + ks * 16 +
                        (lane >> 4) * 8) * 2;
        ldm4(QH[ks], qshb + off);
        ldm4(QL[ks], qslb + off);
    }

    float mi1 = -1e30f, mi2 = -1e30f, li1 = 0.f, li2 = 0.f;
    float oacc[8][4];
#pragma unroll
    for (int dt = 0; dt < 8; dt++)
#pragma unroll
        for (int k = 0; k < 4; k++) oacc[dt][k] = 0.f;

    for (int t = 0; t < ntiles; t++) {
        cpa_wait0();
        __syncthreads();
        if (t + 1 < ntiles) issueKV((t + 1) & 1, t + 1);

        int buf = t & 1;
        unsigned kshb = s2u(KV0 + buf * 4 * FT_TILE);
        unsigned kslb = kshb + FT_TILE * 2;
        unsigned vshb = kslb + FT_TILE * 2;
        unsigned vslb = vshb + FT_TILE * 2;

        float sacc[8][4];
#pragma unroll
        for (int nt = 0; nt < 8; nt++)
#pragma unroll
            for (int k = 0; k < 4; k++) sacc[nt][k] = 0.f;

#pragma unroll
        for (int ks = 0; ks < 4; ks++) {
            int k = ks * 16;
#pragma unroll
            for (int half = 0; half < 4; half++) {
                unsigned ad = ((half * 16 + ((grp & 2) << 2) + gr) * FT_PITCH + k +
                               (grp & 1) * 8) * 2;
                unsigned tH[4], tL[4];
                ldm4(tH, kshb + ad);
                ldm4(tL, kslb + ad);
                mma_bf16(sacc[2 * half], QH[ks], tH[0], tH[1]);
                mma_bf16(sacc[2 * half], QH[ks], tL[0], tL[1]);
                mma_bf16(sacc[2 * half], QL[ks], tH[0], tH[1]);
                mma_bf16(sacc[2 * half + 1], QH[ks], tH[2], tH[3]);
                mma_bf16(sacc[2 * half + 1], QH[ks], tL[2], tL[3]);
                mma_bf16(sacc[2 * half + 1], QL[ks], tH[2], tH[3]);
            }
        }

        float mn1 = mi1, mn2 = mi2;
#pragma unroll
        for (int nt = 0; nt < 8; nt++) {
            int jg = (t << 6) + nt * 8 + cq * 2;
            sacc[nt][0] = (jg <= cap1) ? sacc[nt][0] : -1e30f;
            sacc[nt][1] = (jg + 1 <= cap1) ? sacc[nt][1] : -1e30f;
            sacc[nt][2] = (jg <= cap2) ? sacc[nt][2] : -1e30f;
            sacc[nt][3] = (jg + 1 <= cap2) ? sacc[nt][3] : -1e30f;
            mn1 = fmaxf(mn1, fmaxf(sacc[nt][0], sacc[nt][1]));
            mn2 = fmaxf(mn2, fmaxf(sacc[nt][2], sacc[nt][3]));
        }
        mn1 = fmaxf(mn1, __shfl_xor_sync(0xffffffffu, mn1, 1));
        mn1 = fmaxf(mn1, __shfl_xor_sync(0xffffffffu, mn1, 2));
        mn2 = fmaxf(mn2, __shfl_xor_sync(0xffffffffu, mn2, 1));
        mn2 = fmaxf(mn2, __shfl_xor_sync(0xffffffffu, mn2, 2));
        float corr1 = ex2f(mi1 - mn1), corr2 = ex2f(mi2 - mn2);
        mi1 = mn1;
        mi2 = mn2;
        float rs1 = 0.f, rs2 = 0.f;
#pragma unroll
        for (int nt = 0; nt < 8; nt++) {
            sacc[nt][0] = ex2f(sacc[nt][0] - mn1);
            sacc[nt][1] = ex2f(sacc[nt][1] - mn1);
            sacc[nt][2] = ex2f(sacc[nt][2] - mn2);
            sacc[nt][3] = ex2f(sacc[nt][3] - mn2);
            rs1 += sacc[nt][0] + sacc[nt][1];
            rs2 += sacc[nt][2] + sacc[nt][3];
        }
        rs1 += __shfl_xor_sync(0xffffffffu, rs1, 1);
        rs1 += __shfl_xor_sync(0xffffffffu, rs1, 2);
        rs2 += __shfl_xor_sync(0xffffffffu, rs2, 1);
        rs2 += __shfl_xor_sync(0xffffffffu, rs2, 2);
        li1 = li1 * corr1 + rs1;
        li2 = li2 * corr2 + rs2;
#pragma unroll
        for (int dt = 0; dt < 8; dt++) {
            oacc[dt][0] *= corr1;
            oacc[dt][1] *= corr1;
            oacc[dt][2] *= corr2;
            oacc[dt][3] *= corr2;
        }

#pragma unroll
        for (int ks = 0; ks < 4; ks++) {
            unsigned ah[4], al[4];
            packsplit(sacc[2 * ks][0], sacc[2 * ks][1], ah[0], al[0]);
            packsplit(sacc[2 * ks][2], sacc[2 * ks][3], ah[1], al[1]);
            packsplit(sacc[2 * ks + 1][0], sacc[2 * ks + 1][1], ah[2], al[2]);
            packsplit(sacc[2 * ks + 1][2], sacc[2 * ks + 1][3], ah[3], al[3]);
#pragma unroll
            for (int dtp = 0; dtp < 4; dtp++) {
                unsigned off = ((ks * 16 + (lane & 15)) * FT_PITCH + dtp * 16 +
                                (lane >> 4) * 8) * 2;
                unsigned BH[4], BL[4];
                ldm4t(BH, vshb + off);
                ldm4t(BL, vslb + off);
                mma_bf16(oacc[2 * dtp], ah, BH[0], BH[1]);
                mma_bf16(oacc[2 * dtp], ah, BL[0], BL[1]);
                mma_bf16(oacc[2 * dtp], al, BH[0], BH[1]);
                mma_bf16(oacc[2 * dtp + 1], ah, BH[2], BH[3]);
                mma_bf16(oacc[2 * dtp + 1], ah, BL[2], BL[3]);
                mma_bf16(oacc[2 * dtp + 1], al, BH[2], BH[3]);
            }
        }
    }

    float inv1 = 1.0f / li1, inv2 = 1.0f / li2;
    int i1 = q0 + warp * 16 + r1;
    int i2 = i1 + 8;
    size_t o1 = ((size_t)(b * LL) + i1) * DD + (h << 6) + cq * 2;
    size_t o2 = ((size_t)(b * LL) + i2) * DD + (h << 6) + cq * 2;
#pragma unroll
    for (int dt = 0; dt < 8; dt++) {
        unsigned hi, lo;
        packsplit(oacc[dt][0] * inv1, oacc[dt][1] * inv1, hi, lo);
        *(unsigned*)&Ohi[o1 + dt * 8] = hi;
        *(unsigned*)&Olo[o1 + dt * 8] = lo;
        packsplit(oacc[dt][2] * inv2, oacc[dt][3] * inv2, hi, lo);
        *(unsigned*)&Ohi[o2 + dt * 8] = hi;
        *(unsigned*)&Olo[o2 + dt * 8] = lo;
    }
}

// ---------------- launch ------------------------------------------------------
extern "C" void kernel_launch(void* const* d_in, const int* in_sizes, int n_in,
                              void* d_out, int out_size) {
    const float* src[3] = {0, 0, 0};
    const float* Wmat[4] = {0, 0, 0, 0};
    const float* invf = 0;
    const void* cand8k[2] = {0, 0};
    int nsrc = 0, nw = 0, nc = 0;
    for (int i = 0; i < n_in; i++) {
        int sz = in_sizes[i];
        if (sz == BB * SS * DD && nsrc < 3) src[nsrc++] = (const float*)d_in[i];
        else if (sz == DD * DD && nw < 4) Wmat[nw++] = (const float*)d_in[i];
        else if (sz == 32) invf = (const float*)d_in[i];
        else if (sz == BB * SS && nc < 2) cand8k[nc++] = d_in[i];
    }
    if (nc == 1) cand8k[1] = cand8k[0];
    float* out = (float*)d_out;

    int *pIdx, *pLen;
    cudaGetSymbolAddress((void**)&pIdx, g_idx);
    cudaGetSymbolAddress((void**)&pLen, g_len);

    __nv_bfloat16 *qh, *ql, *kh, *kl, *vh, *vl;
    __nv_bfloat16 *wqh, *wql, *wkh, *wkl, *wvh, *wvl, *woh, *wol;
    __nv_bfloat16 *ohi, *olo, *qrh, *qrl, *krh, *krl, *vph, *vpl;
    cudaGetSymbolAddress((void**)&qh, g_qh);
    cudaGetSymbolAddress((void**)&ql, g_ql);
    cudaGetSymbolAddress((void**)&kh, g_kh);
    cudaGetSymbolAddress((void**)&kl, g_kl);
    cudaGetSymbolAddress((void**)&vh, g_vh);
    cudaGetSymbolAddress((void**)&vl, g_vl);
    cudaGetSymbolAddress((void**)&wqh, g_wqh);
    cudaGetSymbolAddress((void**)&wql, g_wql);
    cudaGetSymbolAddress((void**)&wkh, g_wkh);
    cudaGetSymbolAddress((void**)&wkl, g_wkl);
    cudaGetSymbolAddress((void**)&wvh, g_wvh);
    cudaGetSymbolAddress((void**)&wvl, g_wvl);
    cudaGetSymbolAddress((void**)&woh, g_woh);
    cudaGetSymbolAddress((void**)&wol, g_wol);
    cudaGetSymbolAddress((void**)&ohi, g_Ohi);
    cudaGetSymbolAddress((void**)&olo, g_Olo);
    cudaGetSymbolAddress((void**)&qrh, g_Qrh);
    cudaGetSymbolAddress((void**)&qrl, g_Qrl);
    cudaGetSymbolAddress((void**)&krh, g_Krh);
    cudaGetSymbolAddress((void**)&krl, g_Krl);
    cudaGetSymbolAddress((void**)&vph, g_Vph);
    cudaGetSymbolAddress((void**)&vpl, g_Vpl);

    cudaFuncSetAttribute(flashmma_kernel, cudaFuncAttributeMaxDynamicSharedMemorySize,
                         FT_SMEM);
    cudaFuncSetAttribute(bgemm_kernel<0>, cudaFuncAttributeMaxDynamicSharedMemorySize,
                         GSMEM_BYTES);
    cudaFuncSetAttribute(bgemm_kernel<1>, cudaFuncAttributeMaxDynamicSharedMemorySize,
                         GSMEM_BYTES);
    cudaFuncSetAttribute(bgemm_kernel<2>, cudaFuncAttributeMaxDynamicSharedMemorySize,
                         GSMEM_BYTES);
    cudaFuncSetAttribute(bgemm_kernel<3>, cudaFuncAttributeMaxDynamicSharedMemorySize,
                         GSMEM_BYTES);

    // streams/events for capture-safe fork-join (created once, reused)
    static cudaStream_t st1 = 0, st2 = 0;
    static cudaEvent_t evR = 0, ev1 = 0, ev2 = 0;
    if (!st1) {
        cudaStreamCreateWithFlags(&st1, cudaStreamNonBlocking);
        cudaStreamCreateWithFlags(&st2, cudaStreamNonBlocking);
        cudaEventCreateWithFlags(&evR, cudaEventDisableTiming);
        cudaEventCreateWithFlags(&ev1, cudaEventDisableTiming);
        cudaEventCreateWithFlags(&ev2, cudaEventDisableTiming);
    }

    const int n4s = BB * SS * DD / 4, n4w = DD * DD / 4;

    cudaEventRecord(evR, 0);
    cudaStreamWaitEvent(st1, evR, 0);
    cudaStreamWaitEvent(st2, evR, 0);

    // ---- stream 1: K chain (fused RoPE; no idx dependency) ----
    split_kernel<<<(n4s + 255) / 256, 256, 0, st1>>>((const float4*)src[1], (uint2*)kh,
                                                     (uint2*)kl, n4s);
    split_kernel<<<(n4w + 255) / 256, 256, 0, st1>>>((const float4*)Wmat[1], (uint2*)wkh,
                                                     (uint2*)wkl, n4w);
    bgemm_kernel<1><<<dim3((BB * SS) / GBM, DD / GBN), 256, GSMEM_BYTES, st1>>>(
        kh, kl, wkh, wkl, 0, krh, krl, pIdx, pLen, invf);
    cudaEventRecord(ev1, st1);

    // ---- stream 0: compact (fast inline detect), then Q chain ----
    compact_kernel<<<BB, 32>>>(cand8k[0], cand8k[1], pIdx, pLen);
    split_kernel<<<(n4s + 255) / 256, 256>>>((const float4*)src[0], (uint2*)qh,
                                             (uint2*)ql, n4s);
    split_kernel<<<(n4w + 255) / 256, 256>>>((const float4*)Wmat[0], (uint2*)wqh,
                                             (uint2*)wql, n4w);
    bgemm_kernel<0><<<dim3((BB * LL) / GBM, DD / GBN), 256, GSMEM_BYTES>>>(
        qh, ql, wqh, wql, 0, qrh, qrl, pIdx, pLen, invf);

    // ---- stream 2: V chain (+Wo split; no idx dependency) ----
    split_kernel<<<(n4s + 255) / 256, 256, 0, st2>>>((const float4*)src[2], (uint2*)vh,
                                                     (uint2*)vl, n4s);
    split_kernel<<<(n4w + 255) / 256, 256, 0, st2>>>((const float4*)Wmat[2], (uint2*)wvh,
                                                     (uint2*)wvl, n4w);
    split_kernel<<<(n4w + 255) / 256, 256, 0, st2>>>((const float4*)Wmat[3], (uint2*)woh,
                                                     (uint2*)wol, n4w);
    bgemm_kernel<3><<<dim3((BB * SS) / GBM, DD / GBN), 256, GSMEM_BYTES, st2>>>(
        vh, vl, wvh, wvl, 0, vph, vpl, pIdx, pLen, invf);
    cudaEventRecord(ev2, st2);

    // ---- join, single flash (heavy-first order), single O-proj ----
    cudaStreamWaitEvent(0, ev1, 0);
    cudaStreamWaitEvent(0, ev2, 0);

    flashmma_kernel<<<dim3(BB * HH, LL / 64), 128, FT_SMEM>>>(
        qrh, qrl, krh, krl, vph, vpl, ohi, olo, pIdx, pLen);

    bgemm_kernel<2><<<dim3((BB * LL) / GBM, DD / GBN), 256, GSMEM_BYTES>>>(
        ohi, olo, woh, wol, out, 0, 0, pIdx, pLen, invf);
}